// round 4
// baseline (speedup 1.0000x reference)
#include <cuda_runtime.h>

#define G_ 10
#define B_ 32768
#define K_ 1024
#define D_ 256

// ---------------- scratch (static __device__, no runtime allocation) ----------------
__device__ float  g_rownorm[G_ * B_];          // ||x||^2 per feature row
__device__ float  g_cbnorm [G_ * K_];          // ||e||^2 per code
__device__ int    g_idx    [G_ * B_];          // argmin indices
__device__ double g_part   [G_ * (B_ / 8)];    // per-block loss partials (deterministic)

// ---------------- packed fp32x2 helpers (sm_103a FFMA2 path) ----------------
__device__ __forceinline__ unsigned long long ffma2(unsigned long long a,
                                                    unsigned long long b,
                                                    unsigned long long c) {
    unsigned long long d;
    asm("fma.rn.f32x2 %0, %1, %2, %3;" : "=l"(d) : "l"(a), "l"(b), "l"(c));
    return d;
}
__device__ __forceinline__ unsigned long long pack2(float x) {
    unsigned long long r;
    asm("mov.b64 %0, {%1, %1};" : "=l"(r) : "f"(x));
    return r;
}

// ---------------- squared-norm kernels: one warp per row of 256 floats ----------------
__global__ void rownorm_kernel(const float* __restrict__ x) {
    int w    = (blockIdx.x * 256 + threadIdx.x) >> 5;   // row index (always in range)
    int lane = threadIdx.x & 31;
    const float4* r = (const float4*)(x + (size_t)w * D_);
    float4 a = r[lane];
    float4 b = r[lane + 32];
    float s = a.x*a.x + a.y*a.y + a.z*a.z + a.w*a.w
            + b.x*b.x + b.y*b.y + b.z*b.z + b.w*b.w;
#pragma unroll
    for (int off = 16; off; off >>= 1) s += __shfl_down_sync(0xffffffffu, s, off);
    if (!lane) g_rownorm[w] = s;
}

__global__ void cbnorm_kernel(const float* __restrict__ cb) {
    int w    = (blockIdx.x * 256 + threadIdx.x) >> 5;
    int lane = threadIdx.x & 31;
    const float4* r = (const float4*)(cb + (size_t)w * D_);
    float4 a = r[lane];
    float4 b = r[lane + 32];
    float s = a.x*a.x + a.y*a.y + a.z*a.z + a.w*a.w
            + b.x*b.x + b.y*b.y + b.z*b.z + b.w*b.w;
#pragma unroll
    for (int off = 16; off; off >>= 1) s += __shfl_down_sync(0xffffffffu, s, off);
    if (!lane) g_cbnorm[w] = s;
}

// ---------------- main fused distance + argmin kernel ----------------
// Block tile: BM=128 rows x BN=128 codes, threads 16x16, thread tile 8x8.
// Accumulators packed pairwise over the code (n) direction as f32x2.
// Smem operands stored TRANSPOSED ([d][m] / [d][n], stride 132 to dodge bank conflicts)
// so inner-loop reads are LDS.128 broadcast/contiguous.
__global__ void __launch_bounds__(256, 2)
vq_main_kernel(const float* __restrict__ feats,
               const float* __restrict__ cb,
               float* __restrict__ out_idx_f) {
    __shared__ float sA[32 * 132];   // feats chunk, transposed
    __shared__ float sB[32 * 132];   // codes chunk, transposed
    __shared__ float sRN[128];       // row norms for this block

    const int g   = blockIdx.y;
    const int m0  = blockIdx.x << 7;
    const int tid = threadIdx.x;
    const int tx  = tid & 15;        // n direction (8 codes each)
    const int ty  = tid >> 4;        // m direction (8 rows each)

    const float* F = feats + ((size_t)g * B_ + m0) * D_;
    const float* C = cb + (size_t)g * K_ * D_;

    if (tid < 128) sRN[tid] = g_rownorm[(size_t)g * B_ + m0 + tid];

    float bestV[8];
    int   bestI[8];
#pragma unroll
    for (int i = 0; i < 8; i++) { bestV[i] = 3.4e38f; bestI[i] = 0; }

    for (int nt = 0; nt < K_ / 128; ++nt) {
        unsigned long long acc[8][4];
#pragma unroll
        for (int i = 0; i < 8; i++)
#pragma unroll
            for (int j = 0; j < 4; j++) acc[i][j] = 0ull;

        const float* Cn = C + (size_t)(nt << 7) * D_;

        for (int dc = 0; dc < D_; dc += 32) {
            __syncthreads();   // protect previous chunk's smem use
            // stage feats [128 rows x 32 d] -> sA[d][m]  (coalesced gmem float4)
#pragma unroll
            for (int it = 0; it < 4; ++it) {
                int f  = (it << 8) + tid;
                int m  = f >> 3;
                int dq = f & 7;
                float4 v = *(const float4*)(F + (size_t)m * D_ + dc + (dq << 2));
                int s0 = (dq << 2) * 132 + m;
                sA[s0]       = v.x;
                sA[s0 + 132] = v.y;
                sA[s0 + 264] = v.z;
                sA[s0 + 396] = v.w;
            }
            // stage codes [128 codes x 32 d] -> sB[d][n]
#pragma unroll
            for (int it = 0; it < 4; ++it) {
                int f  = (it << 8) + tid;
                int n  = f >> 3;
                int dq = f & 7;
                float4 v = *(const float4*)(Cn + (size_t)n * D_ + dc + (dq << 2));
                int s0 = (dq << 2) * 132 + n;
                sB[s0]       = v.x;
                sB[s0 + 132] = v.y;
                sB[s0 + 264] = v.z;
                sB[s0 + 396] = v.w;
            }
            __syncthreads();

#pragma unroll 8
            for (int d = 0; d < 32; ++d) {
                const float* ar = sA + d * 132 + (ty << 3);
                const float* br = sB + d * 132 + (tx << 3);
                float4 a0 = *(const float4*)ar;
                float4 a1 = *(const float4*)(ar + 4);
                ulonglong2 p0 = *(const ulonglong2*)br;        // codes n..n+3 (2 pairs)
                ulonglong2 p1 = *(const ulonglong2*)(br + 4);  // codes n+4..n+7
                unsigned long long b0 = p0.x, b1 = p0.y, b2 = p1.x, b3 = p1.y;
                float av[8] = {a0.x, a0.y, a0.z, a0.w, a1.x, a1.y, a1.z, a1.w};
#pragma unroll
                for (int i = 0; i < 8; i++) {
                    unsigned long long ap = pack2(av[i]);
                    acc[i][0] = ffma2(ap, b0, acc[i][0]);
                    acc[i][1] = ffma2(ap, b1, acc[i][1]);
                    acc[i][2] = ffma2(ap, b2, acc[i][2]);
                    acc[i][3] = ffma2(ap, b3, acc[i][3]);
                }
            }
        }

        // epilogue: d2 = (||x||^2 + ||e||^2) - 2*dot  (mirrors reference rounding),
        // ascending-n scan with strict < keeps the first (lowest) index on ties.
        const float* cnp = g_cbnorm + (size_t)g * K_ + (nt << 7) + (tx << 3);
        float4 c0 = *(const float4*)cnp;
        float4 c1 = *(const float4*)(cnp + 4);
        float cn[8] = {c0.x, c0.y, c0.z, c0.w, c1.x, c1.y, c1.z, c1.w};
        int nbase = (nt << 7) + (tx << 3);
#pragma unroll
        for (int i = 0; i < 8; i++) {
            float rn = sRN[(ty << 3) + i];
#pragma unroll
            for (int j = 0; j < 4; j++) {
                float lo = __uint_as_float((unsigned)(acc[i][j] & 0xffffffffull));
                float hi = __uint_as_float((unsigned)(acc[i][j] >> 32));
                float d20 = (rn + cn[2 * j])     - 2.0f * lo;
                float d21 = (rn + cn[2 * j + 1]) - 2.0f * hi;
                if (d20 < bestV[i]) { bestV[i] = d20; bestI[i] = nbase + 2 * j; }
                if (d21 < bestV[i]) { bestV[i] = d21; bestI[i] = nbase + 2 * j + 1; }
            }
        }
    }

    // cross-thread (tx 0..15 = one half-warp) argmin reduction, lowest-index ties
#pragma unroll
    for (int i = 0; i < 8; i++) {
        float v  = bestV[i];
        int  idx = bestI[i];
#pragma unroll
        for (int off = 1; off < 16; off <<= 1) {
            float ov = __shfl_xor_sync(0xffffffffu, v, off);
            int   oi = __shfl_xor_sync(0xffffffffu, idx, off);
            if (ov < v || (ov == v && oi < idx)) { v = ov; idx = oi; }
        }
        if (tx == 0) {
            size_t r = (size_t)g * B_ + m0 + (ty << 3) + i;
            g_idx[r]     = idx;
            out_idx_f[r] = (float)idx;
        }
    }
}

// ---------------- gather + straight-through output + loss partials ----------------
// One warp per row; deterministic fixed-order reductions (no atomics).
__global__ void gather_kernel(const float* __restrict__ feats,
                              const float* __restrict__ cb,
                              float* __restrict__ out_q) {
    __shared__ double bs[8];
    int g    = blockIdx.y;
    int w    = threadIdx.x >> 5;
    int lane = threadIdx.x & 31;
    size_t row = (size_t)g * B_ + ((size_t)blockIdx.x << 3) + w;
    int idx = g_idx[row];
    const float4* f4 = (const float4*)(feats + row * D_);
    const float4* q4 = (const float4*)(cb + ((size_t)g * K_ + idx) * D_);
    float4* o4 = (float4*)(out_q + row * D_);

    float sl = 0.0f;
#pragma unroll
    for (int it = 0; it < 2; ++it) {
        int p = lane + (it << 5);
        float4 f = f4[p];
        float4 q = q4[p];
        float4 o;
        float t;
        t = q.x - f.x; o.x = f.x + t; sl += t * t;   // feats + sg(quant - feats)
        t = q.y - f.y; o.y = f.y + t; sl += t * t;
        t = q.z - f.z; o.z = f.z + t; sl += t * t;
        t = q.w - f.w; o.w = f.w + t; sl += t * t;
        o4[p] = o;
    }
    double s = (double)sl;
#pragma unroll
    for (int off = 16; off; off >>= 1) s += __shfl_down_sync(0xffffffffu, s, off);
    if (!lane) bs[w] = s;
    __syncthreads();
    if (!threadIdx.x) {
        double tot = 0.0;
#pragma unroll
        for (int i = 0; i < 8; i++) tot += bs[i];
        g_part[(size_t)g * (B_ / 8) + blockIdx.x] = tot;
    }
}

// ---------------- deterministic loss finalize ----------------
__global__ void finalize_kernel(float* __restrict__ out_loss) {
    __shared__ double sh[256];
    __shared__ float  gm[G_];
    int tid = threadIdx.x;
    for (int g = 0; g < G_; ++g) {
        double s = 0.0;
        for (int i = tid; i < B_ / 8; i += 256) s += g_part[(size_t)g * (B_ / 8) + i];
        sh[tid] = s;
        __syncthreads();
        for (int st = 128; st; st >>= 1) {
            if (tid < st) sh[tid] += sh[tid + st];
            __syncthreads();
        }
        if (!tid) gm[g] = (float)(sh[0] / (double)((size_t)B_ * D_));
        __syncthreads();
    }
    if (!tid) {
        const float commit[G_] = {0.5f, 0.5f, 0.4f, 0.4f, 0.4f,
                                  0.4f, 0.8f, 0.8f, 0.8f, 0.8f};
        float total = 0.0f;
        for (int g = 0; g < G_; ++g) {
            float e = gm[g];             // e_latent == q_latent numerically
            total += e + commit[g] * e;  // q_latent + commit * e_latent
        }
        *out_loss = total;
    }
}

// ---------------- launch ----------------
extern "C" void kernel_launch(void* const* d_in, const int* in_sizes, int n_in,
                              void* d_out, int out_size) {
    (void)in_sizes; (void)n_in; (void)out_size;
    const float* feats = (const float*)d_in[0];   // (G,B,D) fp32
    const float* cb    = (const float*)d_in[1];   // (G,K,D) fp32
    float* out      = (float*)d_out;
    float* out_q    = out;                               // (G,B,D)
    float* out_loss = out + (size_t)G_ * B_ * D_;        // scalar
    float* out_idx  = out_loss + 1;                      // (G,B) as float

    rownorm_kernel<<<G_ * B_ / 8, 256>>>(feats);
    cbnorm_kernel <<<G_ * K_ / 8, 256>>>(cb);

    dim3 mg(B_ / 128, G_);
    vq_main_kernel<<<mg, 256>>>(feats, cb, out_idx);

    dim3 gg(B_ / 8, G_);
    gather_kernel<<<gg, 256>>>(feats, cb, out_q);

    finalize_kernel<<<1, 256>>>(out_loss);
}

// round 7
// speedup vs baseline: 1.3584x; 1.3584x over previous
#include <cuda_runtime.h>
#include <cstdint>

#define G_ 10
#define B_ 32768
#define K_ 1024
#define D_ 256

// ==================== static device scratch ====================
__device__ float  g_rownorm[G_ * B_];
__device__ float  g_cbnorm [G_ * K_];
__device__ double g_part   [G_ * (B_ / 8)];
// 32 candidates per row (value = cn - 2*dot_tf32, and index)
__device__ float  g_candV[(size_t)G_ * B_ * 32];
__device__ int    g_candI[(size_t)G_ * B_ * 32];

// ==================== helpers ====================
__device__ __forceinline__ float tf32_rna(float x) {
    uint32_t u;
    asm("cvt.rna.tf32.f32 %0, %1;" : "=r"(u) : "f"(x));
    return __uint_as_float(u);
}

// m16n8k8 tf32 MMA (base sm_80 feature -> compiles for plain sm_103).
__device__ __forceinline__ void mma_tf32(float* c, const uint32_t* a, const uint32_t* b) {
    asm volatile(
        "mma.sync.aligned.m16n8k8.row.col.f32.tf32.tf32.f32 "
        "{%0,%1,%2,%3}, {%4,%5,%6,%7}, {%8,%9}, {%0,%1,%2,%3};"
        : "+f"(c[0]), "+f"(c[1]), "+f"(c[2]), "+f"(c[3])
        : "r"(a[0]), "r"(a[1]), "r"(a[2]), "r"(a[3]), "r"(b[0]), "r"(b[1]));
}

// ==================== norm kernels (proven in R4) ====================
__global__ void rownorm_kernel(const float* __restrict__ x) {
    int w = (blockIdx.x * 256 + threadIdx.x) >> 5;
    int lane = threadIdx.x & 31;
    const float4* r = (const float4*)(x + (size_t)w * D_);
    float4 a = r[lane], b = r[lane + 32];
    float s = a.x*a.x + a.y*a.y + a.z*a.z + a.w*a.w
            + b.x*b.x + b.y*b.y + b.z*b.z + b.w*b.w;
#pragma unroll
    for (int off = 16; off; off >>= 1) s += __shfl_down_sync(0xffffffffu, s, off);
    if (!lane) g_rownorm[w] = s;
}
__global__ void cbnorm_kernel(const float* __restrict__ cb) {
    int w = (blockIdx.x * 256 + threadIdx.x) >> 5;
    int lane = threadIdx.x & 31;
    const float4* r = (const float4*)(cb + (size_t)w * D_);
    float4 a = r[lane], b = r[lane + 32];
    float s = a.x*a.x + a.y*a.y + a.z*a.z + a.w*a.w
            + b.x*b.x + b.y*b.y + b.z*b.z + b.w*b.w;
#pragma unroll
    for (int off = 16; off; off >>= 1) s += __shfl_down_sync(0xffffffffu, s, off);
    if (!lane) g_cbnorm[w] = s;
}

// ==================== phase 1: TF32 GEMM + top-4 candidate capture ====================
// CTA: 256 threads, M-tile 128 rows, loop 8 N-tiles of 128 codes.
// D in 16 chunks of 16, double-buffered smem in mma-fragment order (layout
// validated in R6 — its only failure mode was precision near ties).
// Per (thread,row) a sorted top-4 candidate list lives in smem; each row is
// covered by 8 threads -> 32 candidates/row dumped to gmem scratch.
//
// smem floats: sCN[128] @0 | sCV[4352] @128 | sCI[4352] @4480 | bufs[2*4096] @8832
#define SMEM1_FLOATS 17024

__global__ void __launch_bounds__(256)
vq_tf32_kernel(const float* __restrict__ feats, const float* __restrict__ cb) {
    extern __shared__ float smf[];
    float* sCN = smf;
    float* sCV = smf + 128;
    int*   sCI = (int*)(smf + 4480);

    const int tid  = threadIdx.x;
    const int wid  = tid >> 5;
    const int lane = tid & 31;
    const int g    = blockIdx.y;
    const int m0   = blockIdx.x << 7;
    const int mw   = wid >> 1;
    const int nw   = wid & 1;

    const float* F  = feats + ((size_t)g * B_ + m0) * D_;
    const float* Cg = cb + (size_t)g * K_ * D_;

    // init candidate lists
    for (int i = tid; i < 4352; i += 256) { sCV[i] = 3.4e38f; sCI[i] = 0; }

    // staging constants (R6-validated fragment mapping)
    const int srow = tid >> 1;
    const int kst  = tid & 1;
    const int aMt  = srow >> 4;
    const int aR   = srow & 15;
    const int aOff = (kst * 8 + aMt) * 128 + ((aR & 7) << 2) * 4 + ((aR >> 3) & 1);
    const int bOff = 2048 + (kst * 16 + (srow >> 3)) * 64 + ((srow & 7) << 2) * 2;

    float4 vA0, vA1, vB0, vB1;

    __syncthreads();

    for (int ntile = 0; ntile < 8; ++ntile) {
        const float* Cn = Cg + (size_t)(ntile << 7) * D_;

        float acc[2][8][4];
#pragma unroll
        for (int i = 0; i < 2; ++i)
#pragma unroll
            for (int j = 0; j < 8; ++j)
#pragma unroll
                for (int k = 0; k < 4; ++k) acc[i][j][k] = 0.0f;

        // stage chunk 0, prefetch chunk 1
        {
            const float4* pA = (const float4*)(F  + (size_t)srow * D_ + (kst << 3));
            const float4* pB = (const float4*)(Cn + (size_t)srow * D_ + (kst << 3));
            float4 a0 = pA[0], a1 = pA[1], b0 = pB[0], b1 = pB[1];
            float* buf = smf + 8832;
            float av[8] = {a0.x,a0.y,a0.z,a0.w,a1.x,a1.y,a1.z,a1.w};
            float bv[8] = {b0.x,b0.y,b0.z,b0.w,b1.x,b1.y,b1.z,b1.w};
#pragma unroll
            for (int j = 0; j < 8; ++j) {
                buf[aOff + (j & 3) * 4 + ((j >> 2) << 1)] = tf32_rna(av[j]);
                buf[bOff + (j & 3) * 2 + (j >> 2)]        = tf32_rna(bv[j]);
            }
        }
        {
            const float4* pA = (const float4*)(F  + (size_t)srow * D_ + 16 + (kst << 3));
            const float4* pB = (const float4*)(Cn + (size_t)srow * D_ + 16 + (kst << 3));
            vA0 = pA[0]; vA1 = pA[1]; vB0 = pB[0]; vB1 = pB[1];
        }
        __syncthreads();

        for (int c = 0; c < 16; ++c) {
            const float* buf = smf + 8832 + ((c & 1) << 12);
#pragma unroll
            for (int ks = 0; ks < 2; ++ks) {
                uint32_t aH[2][4];
#pragma unroll
                for (int mti = 0; mti < 2; ++mti) {
                    const float* ap = buf + ((ks << 3) + (mw << 1) + mti) * 128 + (lane << 2);
                    float4 h = *(const float4*)ap;
                    aH[mti][0] = __float_as_uint(h.x); aH[mti][1] = __float_as_uint(h.y);
                    aH[mti][2] = __float_as_uint(h.z); aH[mti][3] = __float_as_uint(h.w);
                }
#pragma unroll
                for (int nt = 0; nt < 8; ++nt) {
                    const float* bp = buf + 2048 + ((ks << 4) + (nw << 3) + nt) * 64 + (lane << 1);
                    float2 h = *(const float2*)bp;
                    uint32_t bH[2] = {__float_as_uint(h.x), __float_as_uint(h.y)};
                    mma_tf32(acc[0][nt], aH[0], bH);
                    mma_tf32(acc[1][nt], aH[1], bH);
                }
            }
            __syncthreads();
            if (c < 15) {
                float* nbuf = smf + 8832 + (((c + 1) & 1) << 12);
                float av[8] = {vA0.x,vA0.y,vA0.z,vA0.w,vA1.x,vA1.y,vA1.z,vA1.w};
                float bv[8] = {vB0.x,vB0.y,vB0.z,vB0.w,vB1.x,vB1.y,vB1.z,vB1.w};
#pragma unroll
                for (int j = 0; j < 8; ++j) {
                    nbuf[aOff + (j & 3) * 4 + ((j >> 2) << 1)] = tf32_rna(av[j]);
                    nbuf[bOff + (j & 3) * 2 + (j >> 2)]        = tf32_rna(bv[j]);
                }
                if (c < 14) {
                    const float4* pA = (const float4*)(F  + (size_t)srow * D_ + ((c + 2) << 4) + (kst << 3));
                    const float4* pB = (const float4*)(Cn + (size_t)srow * D_ + ((c + 2) << 4) + (kst << 3));
                    vA0 = pA[0]; vA1 = pA[1]; vB0 = pB[0]; vB1 = pB[1];
                }
                __syncthreads();
            }
        }

        // ---- epilogue: score = cn - 2*dot, insert into per-(thread,row) top-4 ----
        __syncthreads();
        if (tid < 128) sCN[tid] = g_cbnorm[(size_t)g * K_ + (ntile << 7) + tid];
        __syncthreads();

#pragma unroll
        for (int mti = 0; mti < 2; ++mti)
#pragma unroll
            for (int hf = 0; hf < 2; ++hf) {
                const int base = tid * 17 + (mti * 2 + hf) * 4;
                float* LV = sCV + base;
                int*   LI = sCI + base;
#pragma unroll
                for (int nt = 0; nt < 8; ++nt) {
                    int cl = (nw << 6) + (nt << 3) + ((lane & 3) << 1);
                    int gi = (ntile << 7) + cl;
#pragma unroll
                    for (int cc = 0; cc < 2; ++cc) {
                        float v = sCN[cl + cc] - 2.0f * acc[mti][nt][(hf << 1) + cc];
                        int id = gi + cc;
                        if (v < LV[3]) {
                            if (v < LV[2]) {
                                LV[3] = LV[2]; LI[3] = LI[2];
                                if (v < LV[1]) {
                                    LV[2] = LV[1]; LI[2] = LI[1];
                                    if (v < LV[0]) {
                                        LV[1] = LV[0]; LI[1] = LI[0];
                                        LV[0] = v; LI[0] = id;
                                    } else { LV[1] = v; LI[1] = id; }
                                } else { LV[2] = v; LI[2] = id; }
                            } else { LV[3] = v; LI[3] = id; }
                        }
                    }
                }
            }
    }

    // ---- dump candidates (own slots, no sync needed) ----
#pragma unroll
    for (int mti = 0; mti < 2; ++mti)
#pragma unroll
        for (int hf = 0; hf < 2; ++hf) {
            int rloc = (mw << 5) + (mti << 4) + (hf << 3) + (lane >> 2);
            size_t r = (size_t)g * B_ + m0 + rloc;
            int base = tid * 17 + (mti * 2 + hf) * 4;
            int s8   = (nw << 2) | (lane & 3);
#pragma unroll
            for (int s = 0; s < 4; ++s) {
                g_candV[r * 32 + s8 * 4 + s] = sCV[base + s];
                g_candI[r * 32 + s8 * 4 + s] = sCI[base + s];
            }
        }
}

// ==================== phase 2: exact fp32 rescore + gather + loss ====================
// One warp per row. Exact d2 = (rn + cn) - 2*dot (R4-proven formula/tables)
// on every candidate within EPS of the approx min; lowest index on exact ties.
#define EPS_RESCORE 0.03f

__global__ void rescore_gather_kernel(const float* __restrict__ feats,
                                      const float* __restrict__ cb,
                                      float* __restrict__ out_q,
                                      float* __restrict__ out_idx_f) {
    __shared__ double bs[8];
    const int g = blockIdx.y, w = threadIdx.x >> 5, lane = threadIdx.x & 31;
    const size_t row = (size_t)g * B_ + ((size_t)blockIdx.x << 3) + w;

    float cv = g_candV[row * 32 + lane];
    int   ci = g_candI[row * 32 + lane];

    float vmin = cv;
#pragma unroll
    for (int off = 16; off; off >>= 1)
        vmin = fminf(vmin, __shfl_xor_sync(0xffffffffu, vmin, off));
    unsigned mask = __ballot_sync(0xffffffffu, cv <= vmin + EPS_RESCORE);

    const float4* f4 = (const float4*)(feats + row * D_);
    float4 fa = f4[lane * 2], fb = f4[lane * 2 + 1];
    const float rn = g_rownorm[row];

    float bestV = 3.4e38f;
    int   bestI = 0x7fffffff;
    unsigned m = mask;
    while (m) {
        int j = __ffs(m) - 1;
        m &= m - 1;
        int idx = __shfl_sync(0xffffffffu, ci, j);
        const float4* c4 = (const float4*)(cb + ((size_t)g * K_ + idx) * D_);
        float4 ca = c4[lane * 2], cbv = c4[lane * 2 + 1];
        float p = fa.x*ca.x + fa.y*ca.y + fa.z*ca.z + fa.w*ca.w
                + fb.x*cbv.x + fb.y*cbv.y + fb.z*cbv.z + fb.w*cbv.w;
#pragma unroll
        for (int off = 16; off; off >>= 1) p += __shfl_xor_sync(0xffffffffu, p, off);
        float cn = g_cbnorm[(size_t)g * K_ + idx];
        float d2 = (rn + cn) - 2.0f * p;           // reference rounding structure
        if (d2 < bestV || (d2 == bestV && idx < bestI)) { bestV = d2; bestI = idx; }
    }
    // all lanes hold identical (bestV,bestI): xor-reduced p is lane-uniform.

    // gather + straight-through + loss partial (R4-proven body)
    const float4* q4 = (const float4*)(cb + ((size_t)g * K_ + bestI) * D_);
    float4* o4 = (float4*)(out_q + row * D_);
    float sl = 0.0f;
#pragma unroll
    for (int it = 0; it < 2; ++it) {
        int p = lane + (it << 5);
        float4 f = f4[p], q = q4[p], o;
        float t;
        t = q.x - f.x; o.x = f.x + t; sl += t * t;
        t = q.y - f.y; o.y = f.y + t; sl += t * t;
        t = q.z - f.z; o.z = f.z + t; sl += t * t;
        t = q.w - f.w; o.w = f.w + t; sl += t * t;
        o4[p] = o;
    }
    double s = (double)sl;
#pragma unroll
    for (int off = 16; off; off >>= 1) s += __shfl_down_sync(0xffffffffu, s, off);
    if (!lane) {
        bs[w] = s;
        out_idx_f[row] = (float)bestI;
    }
    __syncthreads();
    if (!threadIdx.x) {
        double tot = 0.0;
#pragma unroll
        for (int i = 0; i < 8; i++) tot += bs[i];
        g_part[(size_t)g * (B_ / 8) + blockIdx.x] = tot;
    }
}

// ==================== deterministic loss finalize (proven) ====================
__global__ void finalize_kernel(float* __restrict__ out_loss) {
    __shared__ double sh[256];
    __shared__ float gm[G_];
    int tid = threadIdx.x;
    for (int g = 0; g < G_; ++g) {
        double s = 0.0;
        for (int i = tid; i < B_ / 8; i += 256) s += g_part[(size_t)g * (B_ / 8) + i];
        sh[tid] = s;
        __syncthreads();
        for (int st = 128; st; st >>= 1) {
            if (tid < st) sh[tid] += sh[tid + st];
            __syncthreads();
        }
        if (!tid) gm[g] = (float)(sh[0] / (double)((size_t)B_ * D_));
        __syncthreads();
    }
    if (!tid) {
        const float commit[G_] = {0.5f, 0.5f, 0.4f, 0.4f, 0.4f,
                                  0.4f, 0.8f, 0.8f, 0.8f, 0.8f};
        float total = 0.0f;
        for (int g = 0; g < G_; ++g) {
            float e = gm[g];
            total += e + commit[g] * e;
        }
        *out_loss = total;
    }
}

// ==================== launch ====================
extern "C" void kernel_launch(void* const* d_in, const int* in_sizes, int n_in,
                              void* d_out, int out_size) {
    (void)in_sizes; (void)n_in; (void)out_size;
    const float* feats = (const float*)d_in[0];
    const float* cb    = (const float*)d_in[1];
    float* out      = (float*)d_out;
    float* out_q    = out;
    float* out_loss = out + (size_t)G_ * B_ * D_;
    float* out_idx  = out_loss + 1;

    cudaFuncSetAttribute(vq_tf32_kernel, cudaFuncAttributeMaxDynamicSharedMemorySize,
                         SMEM1_FLOATS * (int)sizeof(float));

    rownorm_kernel<<<G_ * B_ / 8, 256>>>(feats);
    cbnorm_kernel <<<G_ * K_ / 8, 256>>>(cb);

    dim3 mg(B_ / 128, G_);
    vq_tf32_kernel<<<mg, 256, SMEM1_FLOATS * sizeof(float)>>>(feats, cb);

    dim3 gg(B_ / 8, G_);
    rescore_gather_kernel<<<gg, 256>>>(feats, cb, out_q, out_idx);

    finalize_kernel<<<1, 256>>>(out_loss);
}

// round 8
// speedup vs baseline: 2.6110x; 1.9220x over previous
#include <cuda_runtime.h>
#include <cstdint>

#define G_ 10
#define B_ 32768
#define K_ 1024
#define D_ 256

// ==================== static device scratch ====================
__device__ float    g_rownorm[G_ * B_];
__device__ float    g_cbnorm [G_ * K_];
__device__ double   g_part   [G_ * (B_ / 8)];
__device__ uint32_t g_cand   [(size_t)G_ * B_ * 32];               // packed keys
// TF32 fragment-image copies (2048 floats per (tile,chunk) block)
__device__ float    g_featsTF[(size_t)G_ * (B_ / 128) * 16 * 2048]; // 335.5 MB
__device__ float    g_cbTF   [(size_t)G_ * 8 * 16 * 2048];          // 10.5 MB

// ==================== helpers ====================
__device__ __forceinline__ float tf32_rna(float x) {
    uint32_t u;
    asm("cvt.rna.tf32.f32 %0, %1;" : "=r"(u) : "f"(x));
    return __uint_as_float(u);
}
__device__ __forceinline__ void mma_tf32(float* c, const uint32_t* a, const uint32_t* b) {
    asm volatile(
        "mma.sync.aligned.m16n8k8.row.col.f32.tf32.tf32.f32 "
        "{%0,%1,%2,%3}, {%4,%5,%6,%7}, {%8,%9}, {%0,%1,%2,%3};"
        : "+f"(c[0]), "+f"(c[1]), "+f"(c[2]), "+f"(c[3])
        : "r"(a[0]), "r"(a[1]), "r"(a[2]), "r"(a[3]), "r"(b[0]), "r"(b[1]));
}
__device__ __forceinline__ uint32_t smem_u32(const void* p) {
    uint32_t a;
    asm("{ .reg .u64 t; cvta.to.shared.u64 t, %1; cvt.u32.u64 %0, t; }" : "=r"(a) : "l"(p));
    return a;
}
__device__ __forceinline__ void cp16(uint32_t dst, const float* src) {
    asm volatile("cp.async.cg.shared.global [%0], [%1], 16;" :: "r"(dst), "l"(src));
}
#define CP_COMMIT() asm volatile("cp.async.commit_group;" ::: "memory")
#define CP_WAIT2()  asm volatile("cp.async.wait_group 2;" ::: "memory")

// order-preserving float->uint key with 10-bit index in low bits
__device__ __forceinline__ uint32_t fkey(float v, int idx) {
    uint32_t b = __float_as_uint(v);
    uint32_t u = (b & 0x80000000u) ? ~b : (b | 0x80000000u);
    return (u & 0xFFFFFC00u) | (uint32_t)idx;
}
__device__ __forceinline__ float unkey(uint32_t key) {
    uint32_t u = key & 0xFFFFFC00u;
    uint32_t b = (u & 0x80000000u) ? (u ^ 0x80000000u) : ~u;
    return __uint_as_float(b);
}

// ==================== norm kernels (proven) ====================
__global__ void rownorm_kernel(const float* __restrict__ x) {
    int w = (blockIdx.x * 256 + threadIdx.x) >> 5;
    int lane = threadIdx.x & 31;
    const float4* r = (const float4*)(x + (size_t)w * D_);
    float4 a = r[lane], b = r[lane + 32];
    float s = a.x*a.x + a.y*a.y + a.z*a.z + a.w*a.w
            + b.x*b.x + b.y*b.y + b.z*b.z + b.w*b.w;
#pragma unroll
    for (int off = 16; off; off >>= 1) s += __shfl_down_sync(0xffffffffu, s, off);
    if (!lane) g_rownorm[w] = s;
}
__global__ void cbnorm_kernel(const float* __restrict__ cb) {
    int w = (blockIdx.x * 256 + threadIdx.x) >> 5;
    int lane = threadIdx.x & 31;
    const float4* r = (const float4*)(cb + (size_t)w * D_);
    float4 a = r[lane], b = r[lane + 32];
    float s = a.x*a.x + a.y*a.y + a.z*a.z + a.w*a.w
            + b.x*b.x + b.y*b.y + b.z*b.z + b.w*b.w;
#pragma unroll
    for (int off = 16; off; off >>= 1) s += __shfl_down_sync(0xffffffffu, s, off);
    if (!lane) g_cbnorm[w] = s;
}

// ==================== pre-format kernels ====================
// Build the 2048-float fragment images in gmem. Write-side transform uses the
// EXACT formulas validated in R6/R7 staging; mirrored through smem so both
// gmem read and write are coalesced.
// A image element (srow 0..127, kst 0..1, j 0..7):
//   off = (kst*8 + srow/16)*128 + ((srow&7)<<4) + ((srow>>3)&1) + (j&3)*4 + ((j>>2)<<1)
__global__ void prep_feats_kernel(const float* __restrict__ feats) {
    __shared__ float img[2048];
    const int tid = threadIdx.x;
    const int g = blockIdx.y, mt0 = blockIdx.x;
    const int srow = tid >> 1, kst = tid & 1;
    const int aMt = srow >> 4, aR = srow & 15;
    const int aOff = (kst * 8 + aMt) * 128 + ((aR & 7) << 2) * 4 + ((aR >> 3) & 1);
    const float* F = feats + (((size_t)g * B_ + (mt0 << 7)) + srow) * D_;
    float* dst = g_featsTF + ((size_t)(g * (B_ / 128) + mt0) * 16) * 2048;
    for (int c = 0; c < 16; ++c) {
        const float4* p = (const float4*)(F + (c << 4) + (kst << 3));
        float4 a0 = p[0], a1 = p[1];
        float av[8] = {a0.x,a0.y,a0.z,a0.w,a1.x,a1.y,a1.z,a1.w};
#pragma unroll
        for (int j = 0; j < 8; ++j)
            img[aOff + (j & 3) * 4 + ((j >> 2) << 1)] = tf32_rna(av[j]);
        __syncthreads();
        float4* o = (float4*)(dst + (size_t)c * 2048 + tid * 8);
        o[0] = *(float4*)(img + tid * 8);
        o[1] = *(float4*)(img + tid * 8 + 4);
        __syncthreads();
    }
}
// B image element (n 0..127, kst, j): off = (kst*16 + n/8)*64 + (n&7)*8 + (j&3)*2 + (j>>2)
__global__ void prep_cb_kernel(const float* __restrict__ cb) {
    __shared__ float img[2048];
    const int tid = threadIdx.x;
    const int g = blockIdx.y, ntile = blockIdx.x;
    const int n = tid >> 1, kst = tid & 1;
    const int bOff = (kst * 16 + (n >> 3)) * 64 + ((n & 7) << 2) * 2;
    const float* C = cb + (((size_t)g * K_ + (ntile << 7)) + n) * D_;
    float* dst = g_cbTF + ((size_t)(g * 8 + ntile) * 16) * 2048;
    for (int c = 0; c < 16; ++c) {
        const float4* p = (const float4*)(C + (c << 4) + (kst << 3));
        float4 b0 = p[0], b1 = p[1];
        float bv[8] = {b0.x,b0.y,b0.z,b0.w,b1.x,b1.y,b1.z,b1.w};
#pragma unroll
        for (int j = 0; j < 8; ++j)
            img[bOff + (j & 3) * 2 + (j >> 2)] = tf32_rna(bv[j]);
        __syncthreads();
        float4* o = (float4*)(dst + (size_t)c * 2048 + tid * 8);
        o[0] = *(float4*)(img + tid * 8);
        o[1] = *(float4*)(img + tid * 8 + 4);
        __syncthreads();
    }
}

// ==================== phase 1: lean TF32 GEMM + register top-4 ====================
// 4-stage cp.async ring, 16 KB/stage ([A 2048 f][B 2048 f]); single 128-chunk
// loop (8 ntiles x 16 chunks); epilogue every 16 chunks; top-4 packed keys in
// registers; dump 32 keys/row at the end.
#define STAGES    4
#define STAGE_F   4096          // floats per stage
#define SMEM_GEMM (STAGES * STAGE_F * 4)

__global__ void __launch_bounds__(256, 2)
vq_tf32_kernel() {
    extern __shared__ float smf[];
    const uint32_t sb = smem_u32(smf);
    const int tid  = threadIdx.x;
    const int wid  = tid >> 5;
    const int lane = tid & 31;
    const int g    = blockIdx.y;
    const int mt0  = blockIdx.x;
    const int mw   = wid >> 1;
    const int nw   = wid & 1;

    const float* srcA0 = g_featsTF + ((size_t)(g * (B_ / 128) + mt0) * 16) * 2048;
    const float* srcB0 = g_cbTF + ((size_t)g * 8 * 16) * 2048;

    uint32_t L[4][4];
#pragma unroll
    for (int l = 0; l < 4; ++l)
#pragma unroll
        for (int s = 0; s < 4; ++s) L[l][s] = 0xFFFFFFFFu;

    float acc[2][8][4];
#pragma unroll
    for (int i = 0; i < 2; ++i)
#pragma unroll
        for (int j = 0; j < 8; ++j)
#pragma unroll
            for (int k = 0; k < 4; ++k) acc[i][j][k] = 0.0f;

    // prologue: fill chunks 0..2
#pragma unroll
    for (int cc = 0; cc < 3; ++cc) {
        uint32_t d = sb + cc * (STAGE_F * 4) + tid * 32;
        const float* sa = srcA0 + (size_t)cc * 2048 + tid * 8;
        const float* sbp = srcB0 + (size_t)cc * 2048 + tid * 8;  // cc<16 -> ntile 0
        cp16(d, sa); cp16(d + 16, sa + 4);
        cp16(d + 8192, sbp); cp16(d + 8192 + 16, sbp + 4);
        CP_COMMIT();
    }

    for (int cc = 0; cc < 128; ++cc) {
        CP_WAIT2();
        __syncthreads();
        const float* buf = smf + (cc & 3) * STAGE_F;

        // ---- MMA on chunk cc (R6/R7-validated fragment reads) ----
#pragma unroll
        for (int ks = 0; ks < 2; ++ks) {
            uint32_t aH[2][4];
#pragma unroll
            for (int mti = 0; mti < 2; ++mti) {
                const float* ap = buf + ((ks << 3) + (mw << 1) + mti) * 128 + (lane << 2);
                float4 h = *(const float4*)ap;
                aH[mti][0] = __float_as_uint(h.x); aH[mti][1] = __float_as_uint(h.y);
                aH[mti][2] = __float_as_uint(h.z); aH[mti][3] = __float_as_uint(h.w);
            }
#pragma unroll
            for (int nt = 0; nt < 8; ++nt) {
                const float* bp = buf + 2048 + ((ks << 4) + (nw << 3) + nt) * 64 + (lane << 1);
                float2 h = *(const float2*)bp;
                uint32_t bH[2] = {__float_as_uint(h.x), __float_as_uint(h.y)};
                mma_tf32(acc[0][nt], aH[0], bH);
                mma_tf32(acc[1][nt], aH[1], bH);
            }
        }

        // ---- refill stage cc+3 ----
        if (cc + 3 < 128) {
            const int nc = cc + 3;
            uint32_t d = sb + (nc & 3) * (STAGE_F * 4) + tid * 32;
            const float* sa = srcA0 + (size_t)(nc & 15) * 2048 + tid * 8;
            const float* sbp = srcB0 + ((size_t)(nc >> 4) * 16 + (nc & 15)) * 2048 + tid * 8;
            cp16(d, sa); cp16(d + 16, sa + 4);
            cp16(d + 8192, sbp); cp16(d + 8192 + 16, sbp + 4);
        }
        CP_COMMIT();

        // ---- epilogue at end of each ntile ----
        if ((cc & 15) == 15) {
            const int ntile = cc >> 4;
            const float* cnb = g_cbnorm + (size_t)g * K_ + (ntile << 7);
#pragma unroll
            for (int nt = 0; nt < 8; ++nt) {
                int cl = (nw << 6) + (nt << 3) + ((lane & 3) << 1);
                float cn0 = __ldg(cnb + cl), cn1 = __ldg(cnb + cl + 1);
                int gi = (ntile << 7) + cl;
#pragma unroll
                for (int l = 0; l < 4; ++l) {
                    const int mti = l >> 1, hf = l & 1;
                    float v0 = cn0 - 2.0f * acc[mti][nt][(hf << 1)];
                    float v1 = cn1 - 2.0f * acc[mti][nt][(hf << 1) + 1];
                    uint32_t k0 = fkey(v0, gi), k1 = fkey(v1, gi + 1);
#pragma unroll
                    for (int pick = 0; pick < 2; ++pick) {
                        uint32_t k = pick ? k1 : k0;
                        if (k < L[l][3]) {
                            if (k < L[l][2]) {
                                L[l][3] = L[l][2];
                                if (k < L[l][1]) {
                                    L[l][2] = L[l][1];
                                    if (k < L[l][0]) { L[l][1] = L[l][0]; L[l][0] = k; }
                                    else             { L[l][1] = k; }
                                } else { L[l][2] = k; }
                            } else { L[l][3] = k; }
                        }
                    }
                }
            }
#pragma unroll
            for (int i = 0; i < 2; ++i)
#pragma unroll
                for (int j = 0; j < 8; ++j)
#pragma unroll
                    for (int k = 0; k < 4; ++k) acc[i][j][k] = 0.0f;
        }
    }

    // ---- dump 32 keys per row ----
#pragma unroll
    for (int l = 0; l < 4; ++l) {
        const int mti = l >> 1, hf = l & 1;
        int rloc = (mw << 5) + (mti << 4) + (hf << 3) + (lane >> 2);
        size_t r = (size_t)g * B_ + (mt0 << 7) + rloc;
        int s8 = (nw << 2) | (lane & 3);
#pragma unroll
        for (int s = 0; s < 4; ++s)
            g_cand[r * 32 + s8 * 4 + s] = L[l][s];
    }
}

// ==================== phase 2: exact fp32 rescore + gather + loss ====================
#define EPS_RESCORE 0.03f

__global__ void rescore_gather_kernel(const float* __restrict__ feats,
                                      const float* __restrict__ cb,
                                      float* __restrict__ out_q,
                                      float* __restrict__ out_idx_f) {
    __shared__ double bs[8];
    const int g = blockIdx.y, w = threadIdx.x >> 5, lane = threadIdx.x & 31;
    const size_t row = (size_t)g * B_ + ((size_t)blockIdx.x << 3) + w;

    uint32_t key = g_cand[row * 32 + lane];
    int   ci = (int)(key & 1023u);
    float cv = unkey(key);

    uint32_t kmin = key;
#pragma unroll
    for (int off = 16; off; off >>= 1)
        kmin = min(kmin, __shfl_xor_sync(0xffffffffu, kmin, off));
    float vminf = unkey(kmin);
    unsigned mask = __ballot_sync(0xffffffffu, cv <= vminf + EPS_RESCORE);

    const float4* f4 = (const float4*)(feats + row * D_);
    float4 fa = f4[lane * 2], fb = f4[lane * 2 + 1];
    const float rn = g_rownorm[row];

    float bestV = 3.4e38f;
    int   bestI = 0x7fffffff;
    unsigned m = mask;
    while (m) {
        int j = __ffs(m) - 1;
        m &= m - 1;
        int idx = __shfl_sync(0xffffffffu, ci, j);
        const float4* c4 = (const float4*)(cb + ((size_t)g * K_ + idx) * D_);
        float4 ca = c4[lane * 2], cbv = c4[lane * 2 + 1];
        float p = fa.x*ca.x + fa.y*ca.y + fa.z*ca.z + fa.w*ca.w
                + fb.x*cbv.x + fb.y*cbv.y + fb.z*cbv.z + fb.w*cbv.w;
#pragma unroll
        for (int off = 16; off; off >>= 1) p += __shfl_xor_sync(0xffffffffu, p, off);
        float cn = g_cbnorm[(size_t)g * K_ + idx];
        float d2 = (rn + cn) - 2.0f * p;           // reference rounding structure
        if (d2 < bestV || (d2 == bestV && idx < bestI)) { bestV = d2; bestI = idx; }
    }

    const float4* q4 = (const float4*)(cb + ((size_t)g * K_ + bestI) * D_);
    float4* o4 = (float4*)(out_q + row * D_);
    float sl = 0.0f;
#pragma unroll
    for (int it = 0; it < 2; ++it) {
        int p = lane + (it << 5);
        float4 f = f4[p], q = q4[p], o;
        float t;
        t = q.x - f.x; o.x = f.x + t; sl += t * t;
        t = q.y - f.y; o.y = f.y + t; sl += t * t;
        t = q.z - f.z; o.z = f.z + t; sl += t * t;
        t = q.w - f.w; o.w = f.w + t; sl += t * t;
        o4[p] = o;
    }
    double s = (double)sl;
#pragma unroll
    for (int off = 16; off; off >>= 1) s += __shfl_down_sync(0xffffffffu, s, off);
    if (!lane) {
        bs[w] = s;
        out_idx_f[row] = (float)bestI;
    }
    __syncthreads();
    if (!threadIdx.x) {
        double tot = 0.0;
#pragma unroll
        for (int i = 0; i < 8; i++) tot += bs[i];
        g_part[(size_t)g * (B_ / 8) + blockIdx.x] = tot;
    }
}

// ==================== deterministic loss finalize (proven) ====================
__global__ void finalize_kernel(float* __restrict__ out_loss) {
    __shared__ double sh[256];
    __shared__ float gm[G_];
    int tid = threadIdx.x;
    for (int g = 0; g < G_; ++g) {
        double s = 0.0;
        for (int i = tid; i < B_ / 8; i += 256) s += g_part[(size_t)g * (B_ / 8) + i];
        sh[tid] = s;
        __syncthreads();
        for (int st = 128; st; st >>= 1) {
            if (tid < st) sh[tid] += sh[tid + st];
            __syncthreads();
        }
        if (!tid) gm[g] = (float)(sh[0] / (double)((size_t)B_ * D_));
        __syncthreads();
    }
    if (!tid) {
        const float commit[G_] = {0.5f, 0.5f, 0.4f, 0.4f, 0.4f,
                                  0.4f, 0.8f, 0.8f, 0.8f, 0.8f};
        float total = 0.0f;
        for (int g = 0; g < G_; ++g) {
            float e = gm[g];
            total += e + commit[g] * e;
        }
        *out_loss = total;
    }
}

// ==================== launch ====================
extern "C" void kernel_launch(void* const* d_in, const int* in_sizes, int n_in,
                              void* d_out, int out_size) {
    (void)in_sizes; (void)n_in; (void)out_size;
    const float* feats = (const float*)d_in[0];
    const float* cb    = (const float*)d_in[1];
    float* out      = (float*)d_out;
    float* out_q    = out;
    float* out_loss = out + (size_t)G_ * B_ * D_;
    float* out_idx  = out_loss + 1;

    cudaFuncSetAttribute(vq_tf32_kernel, cudaFuncAttributeMaxDynamicSharedMemorySize,
                         SMEM_GEMM);

    rownorm_kernel<<<G_ * B_ / 8, 256>>>(feats);
    cbnorm_kernel <<<G_ * K_ / 8, 256>>>(cb);

    dim3 pf(B_ / 128, G_);
    prep_feats_kernel<<<pf, 256>>>(feats);
    dim3 pc(8, G_);
    prep_cb_kernel<<<pc, 256>>>(cb);

    dim3 mg(B_ / 128, G_);
    vq_tf32_kernel<<<mg, 256, SMEM_GEMM>>>();

    dim3 gg(B_ / 8, G_);
    rescore_gather_kernel<<<gg, 256>>>(feats, cb, out_q, out_idx);

    finalize_kernel<<<1, 256>>>(out_loss);
}

// round 9
// speedup vs baseline: 3.6816x; 1.4100x over previous
#include <cuda_runtime.h>
#include <cuda_fp16.h>
#include <cstdint>

#define G_ 10
#define B_ 32768
#define K_ 1024
#define D_ 256

// ==================== static device scratch ====================
__device__ float    g_rownorm[G_ * B_];
__device__ float    g_cbnorm [G_ * K_];
__device__ double   g_part   [G_ * (B_ / 8)];
__device__ uint32_t g_cand   [(size_t)G_ * B_ * 32];               // packed keys
// FP16 fragment-image copies: 4096 halves per (tile, 32d-chunk) block
__device__ __half   g_featsH[(size_t)G_ * (B_ / 128) * 8 * 4096];   // 168 MB
__device__ __half   g_cbH   [(size_t)G_ * 8 * 8 * 4096];            // 5.25 MB

// ==================== helpers ====================
__device__ __forceinline__ void mma_f16(float* c, const uint32_t* a, const uint32_t* b) {
    asm volatile(
        "mma.sync.aligned.m16n8k16.row.col.f32.f16.f16.f32 "
        "{%0,%1,%2,%3}, {%4,%5,%6,%7}, {%8,%9}, {%0,%1,%2,%3};"
        : "+f"(c[0]), "+f"(c[1]), "+f"(c[2]), "+f"(c[3])
        : "r"(a[0]), "r"(a[1]), "r"(a[2]), "r"(a[3]), "r"(b[0]), "r"(b[1]));
}
__device__ __forceinline__ uint32_t smem_u32(const void* p) {
    uint32_t a;
    asm("{ .reg .u64 t; cvta.to.shared.u64 t, %1; cvt.u32.u64 %0, t; }" : "=r"(a) : "l"(p));
    return a;
}
__device__ __forceinline__ void cp16(uint32_t dst, const void* src) {
    asm volatile("cp.async.cg.shared.global [%0], [%1], 16;" :: "r"(dst), "l"(src));
}
#define CP_COMMIT() asm volatile("cp.async.commit_group;" ::: "memory")
#define CP_WAIT2()  asm volatile("cp.async.wait_group 2;" ::: "memory")

// order-preserving float->uint key with 10-bit index in low bits
__device__ __forceinline__ uint32_t fkey(float v, int idx) {
    uint32_t b = __float_as_uint(v);
    uint32_t u = (b & 0x80000000u) ? ~b : (b | 0x80000000u);
    return (u & 0xFFFFFC00u) | (uint32_t)idx;
}
__device__ __forceinline__ float unkey(uint32_t key) {
    uint32_t u = key & 0xFFFFFC00u;
    uint32_t b = (u & 0x80000000u) ? (u ^ 0x80000000u) : ~u;
    return __uint_as_float(b);
}

// ==================== norm kernels (proven, bit-identical rn/cn) ====================
__global__ void rownorm_kernel(const float* __restrict__ x) {
    int w = (blockIdx.x * 256 + threadIdx.x) >> 5;
    int lane = threadIdx.x & 31;
    const float4* r = (const float4*)(x + (size_t)w * D_);
    float4 a = r[lane], b = r[lane + 32];
    float s = a.x*a.x + a.y*a.y + a.z*a.z + a.w*a.w
            + b.x*b.x + b.y*b.y + b.z*b.z + b.w*b.w;
#pragma unroll
    for (int off = 16; off; off >>= 1) s += __shfl_down_sync(0xffffffffu, s, off);
    if (!lane) g_rownorm[w] = s;
}
__global__ void cbnorm_kernel(const float* __restrict__ cb) {
    int w = (blockIdx.x * 256 + threadIdx.x) >> 5;
    int lane = threadIdx.x & 31;
    const float4* r = (const float4*)(cb + (size_t)w * D_);
    float4 a = r[lane], b = r[lane + 32];
    float s = a.x*a.x + a.y*a.y + a.z*a.z + a.w*a.w
            + b.x*b.x + b.y*b.y + b.z*b.z + b.w*b.w;
#pragma unroll
    for (int off = 16; off; off >>= 1) s += __shfl_down_sync(0xffffffffu, s, off);
    if (!lane) g_cbnorm[w] = s;
}

// ==================== pre-format kernels (fp16 fragment images) ====================
// m16n8k16 fragment layouts (PTX ISA):
//  A elem (r=m&15, k 0..15): lane=((r&7)<<2)|((k&7)>>1); reg=((k>>3)<<1)|(r>>3); half=k&1
//  B elem (c=n&7,  k 0..15): lane=(c<<2)|((k&7)>>1);     reg=k>>3;              half=k&1
// Chunk = 32 d = 2 k16-steps (ks). A block: off = ks*2048 + (m>>4)*256 + lane*8 + reg*2 + half
// B block: off = ks*2048 + (n>>3)*128 + lane*4 + reg*2 + half.  4096 halves per chunk block.
__global__ void prep_feats_kernel(const float* __restrict__ feats) {
    __shared__ __align__(16) __half img[4096];
    const int tid = threadIdx.x;
    const int g = blockIdx.y, mt0 = blockIdx.x;
    const int srow = tid >> 1, ks = tid & 1;
    const int r = srow & 15, mt = srow >> 4;
    const float* F = feats + (((size_t)g * B_ + (mt0 << 7)) + srow) * D_;
    __half* dst = g_featsH + (size_t)(g * (B_ / 128) + mt0) * 8 * 4096;
    for (int c = 0; c < 8; ++c) {
        const float4* p = (const float4*)(F + (c << 5) + (ks << 4));
        float4 t0 = p[0], t1 = p[1], t2 = p[2], t3 = p[3];
        float v[16] = {t0.x,t0.y,t0.z,t0.w, t1.x,t1.y,t1.z,t1.w,
                       t2.x,t2.y,t2.z,t2.w, t3.x,t3.y,t3.z,t3.w};
#pragma unroll
        for (int jj = 0; jj < 16; jj += 2) {
            int lane = ((r & 7) << 2) | ((jj & 7) >> 1);
            int reg  = ((jj >> 3) << 1) | (r >> 3);
            int off  = ks * 2048 + mt * 256 + lane * 8 + reg * 2;
            *(__half2*)(img + off) = __floats2half2_rn(v[jj], v[jj + 1]);
        }
        __syncthreads();
        float4* o = (float4*)(dst + (size_t)c * 4096 + tid * 16);
        const float4* s = (const float4*)(img + tid * 16);
        o[0] = s[0]; o[1] = s[1];
        __syncthreads();
    }
}
__global__ void prep_cb_kernel(const float* __restrict__ cb) {
    __shared__ __align__(16) __half img[4096];
    const int tid = threadIdx.x;
    const int g = blockIdx.y, nt0 = blockIdx.x;
    const int n = tid >> 1, ks = tid & 1;
    const float* C = cb + (((size_t)g * K_ + (nt0 << 7)) + n) * D_;
    __half* dst = g_cbH + (size_t)(g * 8 + nt0) * 8 * 4096;
    for (int c = 0; c < 8; ++c) {
        const float4* p = (const float4*)(C + (c << 5) + (ks << 4));
        float4 t0 = p[0], t1 = p[1], t2 = p[2], t3 = p[3];
        float v[16] = {t0.x,t0.y,t0.z,t0.w, t1.x,t1.y,t1.z,t1.w,
                       t2.x,t2.y,t2.z,t2.w, t3.x,t3.y,t3.z,t3.w};
#pragma unroll
        for (int jj = 0; jj < 16; jj += 2) {
            int lane = ((n & 7) << 2) | ((jj & 7) >> 1);
            int reg  = jj >> 3;
            int off  = ks * 2048 + (n >> 3) * 128 + lane * 4 + reg * 2;
            *(__half2*)(img + off) = __floats2half2_rn(v[jj], v[jj + 1]);
        }
        __syncthreads();
        float4* o = (float4*)(dst + (size_t)c * 4096 + tid * 16);
        const float4* s = (const float4*)(img + tid * 16);
        o[0] = s[0]; o[1] = s[1];
        __syncthreads();
    }
}

// ==================== phase 1: fp16 GEMM + register top-4 ====================
// CTA 128 rows x 128 codes, 8 warps (mw 0..3 x nw 0..1), warp tile 32x64.
// 64 chunks total (8 ntiles x 8 chunks of 32 d). 4-stage ring, 16 KB/stage
// ([A 4096 h][B 4096 h]); wait_group 2 (distance-3 prefetch).
#define STAGE_H   8192
#define SMEM_GEMM (4 * STAGE_H * 2)   // 64 KB

__global__ void __launch_bounds__(256, 2)
vq_f16_kernel() {
    extern __shared__ __half smh[];
    const uint32_t sb = smem_u32(smh);
    const int tid  = threadIdx.x;
    const int wid  = tid >> 5;
    const int lane = tid & 31;
    const int g    = blockIdx.y;
    const int mt0  = blockIdx.x;
    const int mw   = wid >> 1;
    const int nw   = wid & 1;

    const __half* srcA0 = g_featsH + (size_t)(g * (B_ / 128) + mt0) * 8 * 4096;
    const __half* srcB0 = g_cbH + (size_t)g * 8 * 8 * 4096;

    uint32_t L[4][4];
#pragma unroll
    for (int l = 0; l < 4; ++l)
#pragma unroll
        for (int s = 0; s < 4; ++s) L[l][s] = 0xFFFFFFFFu;

    float acc[2][8][4];
#pragma unroll
    for (int i = 0; i < 2; ++i)
#pragma unroll
        for (int j = 0; j < 8; ++j)
#pragma unroll
            for (int k = 0; k < 4; ++k) acc[i][j][k] = 0.0f;

    // prologue: chunks 0..2 (all in ntile 0)
#pragma unroll
    for (int cc = 0; cc < 3; ++cc) {
        uint32_t d = sb + cc * (STAGE_H * 2) + tid * 32;
        const __half* sa  = srcA0 + (size_t)cc * 4096 + tid * 16;
        const __half* sbp = srcB0 + (size_t)cc * 4096 + tid * 16;
        cp16(d, sa); cp16(d + 16, sa + 8);
        cp16(d + 8192, sbp); cp16(d + 8192 + 16, sbp + 8);
        CP_COMMIT();
    }

    for (int cc = 0; cc < 64; ++cc) {
        CP_WAIT2();
        __syncthreads();
        const __half* buf = smh + (cc & 3) * STAGE_H;

        // ---- MMA on chunk cc ----
#pragma unroll
        for (int ks = 0; ks < 2; ++ks) {
            uint32_t aF[2][4];
#pragma unroll
            for (int mti = 0; mti < 2; ++mti) {
                uint4 t = *(const uint4*)(buf + ks * 2048 + ((mw << 1) + mti) * 256 + lane * 8);
                aF[mti][0] = t.x; aF[mti][1] = t.y; aF[mti][2] = t.z; aF[mti][3] = t.w;
            }
#pragma unroll
            for (int nt = 0; nt < 8; ++nt) {
                uint2 bt = *(const uint2*)(buf + 4096 + ks * 2048 + ((nw << 3) + nt) * 128 + lane * 4);
                uint32_t bF[2] = {bt.x, bt.y};
                mma_f16(acc[0][nt], aF[0], bF);
                mma_f16(acc[1][nt], aF[1], bF);
            }
        }

        // ---- refill stage cc+3 ----
        if (cc + 3 < 64) {
            const int nc = cc + 3;
            uint32_t d = sb + (nc & 3) * (STAGE_H * 2) + tid * 32;
            const __half* sa  = srcA0 + (size_t)(nc & 7) * 4096 + tid * 16;
            const __half* sbp = srcB0 + ((size_t)(nc >> 3) * 8 + (nc & 7)) * 4096 + tid * 16;
            cp16(d, sa); cp16(d + 16, sa + 8);
            cp16(d + 8192, sbp); cp16(d + 8192 + 16, sbp + 8);
        }
        CP_COMMIT();

        // ---- epilogue at end of each ntile (every 8 chunks) ----
        if ((cc & 7) == 7) {
            const int ntile = cc >> 3;
            const float* cnb = g_cbnorm + (size_t)g * K_ + (ntile << 7);
#pragma unroll
            for (int nt = 0; nt < 8; ++nt) {
                int cl = (nw << 6) + (nt << 3) + ((lane & 3) << 1);
                float cn0 = __ldg(cnb + cl), cn1 = __ldg(cnb + cl + 1);
                int gi = (ntile << 7) + cl;
#pragma unroll
                for (int l = 0; l < 4; ++l) {
                    const int mti = l >> 1, hf = l & 1;
                    float v0 = cn0 - 2.0f * acc[mti][nt][(hf << 1)];
                    float v1 = cn1 - 2.0f * acc[mti][nt][(hf << 1) + 1];
                    uint32_t k0 = fkey(v0, gi), k1 = fkey(v1, gi + 1);
#pragma unroll
                    for (int pick = 0; pick < 2; ++pick) {
                        uint32_t k = pick ? k1 : k0;
                        if (k < L[l][3]) {
                            if (k < L[l][2]) {
                                L[l][3] = L[l][2];
                                if (k < L[l][1]) {
                                    L[l][2] = L[l][1];
                                    if (k < L[l][0]) { L[l][1] = L[l][0]; L[l][0] = k; }
                                    else             { L[l][1] = k; }
                                } else { L[l][2] = k; }
                            } else { L[l][3] = k; }
                        }
                    }
                }
            }
#pragma unroll
            for (int i = 0; i < 2; ++i)
#pragma unroll
                for (int j = 0; j < 8; ++j)
#pragma unroll
                    for (int k = 0; k < 4; ++k) acc[i][j][k] = 0.0f;
        }
    }

    // ---- dump 32 keys per row ----
#pragma unroll
    for (int l = 0; l < 4; ++l) {
        const int mti = l >> 1, hf = l & 1;
        int rloc = (mw << 5) + (mti << 4) + (hf << 3) + (lane >> 2);
        size_t r = (size_t)g * B_ + (mt0 << 7) + rloc;
        int s8 = (nw << 2) | (lane & 3);
#pragma unroll
        for (int s = 0; s < 4; ++s)
            g_cand[r * 32 + s8 * 4 + s] = L[l][s];
    }
}

// ==================== phase 2: exact fp32 rescore + gather + loss (proven) ====================
#define EPS_RESCORE 0.03f

__global__ void rescore_gather_kernel(const float* __restrict__ feats,
                                      const float* __restrict__ cb,
                                      float* __restrict__ out_q,
                                      float* __restrict__ out_idx_f) {
    __shared__ double bs[8];
    const int g = blockIdx.y, w = threadIdx.x >> 5, lane = threadIdx.x & 31;
    const size_t row = (size_t)g * B_ + ((size_t)blockIdx.x << 3) + w;

    uint32_t key = g_cand[row * 32 + lane];
    int   ci = (int)(key & 1023u);
    float cv = unkey(key);

    uint32_t kmin = key;
#pragma unroll
    for (int off = 16; off; off >>= 1)
        kmin = min(kmin, __shfl_xor_sync(0xffffffffu, kmin, off));
    float vminf = unkey(kmin);
    unsigned mask = __ballot_sync(0xffffffffu, cv <= vminf + EPS_RESCORE);

    const float4* f4 = (const float4*)(feats + row * D_);
    float4 fa = f4[lane * 2], fb = f4[lane * 2 + 1];
    const float rn = g_rownorm[row];

    float bestV = 3.4e38f;
    int   bestI = 0x7fffffff;
    unsigned m = mask;
    while (m) {
        int j = __ffs(m) - 1;
        m &= m - 1;
        int idx = __shfl_sync(0xffffffffu, ci, j);
        const float4* c4 = (const float4*)(cb + ((size_t)g * K_ + idx) * D_);
        float4 ca = c4[lane * 2], cbv = c4[lane * 2 + 1];
        float p = fa.x*ca.x + fa.y*ca.y + fa.z*ca.z + fa.w*ca.w
                + fb.x*cbv.x + fb.y*cbv.y + fb.z*cbv.z + fb.w*cbv.w;
#pragma unroll
        for (int off = 16; off; off >>= 1) p += __shfl_xor_sync(0xffffffffu, p, off);
        float cn = g_cbnorm[(size_t)g * K_ + idx];
        float d2 = (rn + cn) - 2.0f * p;           // reference rounding structure
        if (d2 < bestV || (d2 == bestV && idx < bestI)) { bestV = d2; bestI = idx; }
    }

    const float4* q4 = (const float4*)(cb + ((size_t)g * K_ + bestI) * D_);
    float4* o4 = (float4*)(out_q + row * D_);
    float sl = 0.0f;
#pragma unroll
    for (int it = 0; it < 2; ++it) {
        int p = lane + (it << 5);
        float4 f = f4[p], q = q4[p], o;
        float t;
        t = q.x - f.x; o.x = f.x + t; sl += t * t;
        t = q.y - f.y; o.y = f.y + t; sl += t * t;
        t = q.z - f.z; o.z = f.z + t; sl += t * t;
        t = q.w - f.w; o.w = f.w + t; sl += t * t;
        o4[p] = o;
    }
    double s = (double)sl;
#pragma unroll
    for (int off = 16; off; off >>= 1) s += __shfl_down_sync(0xffffffffu, s, off);
    if (!lane) {
        bs[w] = s;
        out_idx_f[row] = (float)bestI;
    }
    __syncthreads();
    if (!threadIdx.x) {
        double tot = 0.0;
#pragma unroll
        for (int i = 0; i < 8; i++) tot += bs[i];
        g_part[(size_t)g * (B_ / 8) + blockIdx.x] = tot;
    }
}

// ==================== deterministic loss finalize (proven) ====================
__global__ void finalize_kernel(float* __restrict__ out_loss) {
    __shared__ double sh[256];
    __shared__ float gm[G_];
    int tid = threadIdx.x;
    for (int g = 0; g < G_; ++g) {
        double s = 0.0;
        for (int i = tid; i < B_ / 8; i += 256) s += g_part[(size_t)g * (B_ / 8) + i];
        sh[tid] = s;
        __syncthreads();
        for (int st = 128; st; st >>= 1) {
            if (tid < st) sh[tid] += sh[tid + st];
            __syncthreads();
        }
        if (!tid) gm[g] = (float)(sh[0] / (double)((size_t)B_ * D_));
        __syncthreads();
    }
    if (!tid) {
        const float commit[G_] = {0.5f, 0.5f, 0.4f, 0.4f, 0.4f,
                                  0.4f, 0.8f, 0.8f, 0.8f, 0.8f};
        float total = 0.0f;
        for (int g = 0; g < G_; ++g) {
            float e = gm[g];
            total += e + commit[g] * e;
        }
        *out_loss = total;
    }
}

// ==================== launch ====================
extern "C" void kernel_launch(void* const* d_in, const int* in_sizes, int n_in,
                              void* d_out, int out_size) {
    (void)in_sizes; (void)n_in; (void)out_size;
    const float* feats = (const float*)d_in[0];
    const float* cb    = (const float*)d_in[1];
    float* out      = (float*)d_out;
    float* out_q    = out;
    float* out_loss = out + (size_t)G_ * B_ * D_;
    float* out_idx  = out_loss + 1;

    cudaFuncSetAttribute(vq_f16_kernel, cudaFuncAttributeMaxDynamicSharedMemorySize,
                         SMEM_GEMM);

    rownorm_kernel<<<G_ * B_ / 8, 256>>>(feats);
    cbnorm_kernel <<<G_ * K_ / 8, 256>>>(cb);

    dim3 pf(B_ / 128, G_);
    prep_feats_kernel<<<pf, 256>>>(feats);
    dim3 pc(8, G_);
    prep_cb_kernel<<<pc, 256>>>(cb);

    dim3 mg(B_ / 128, G_);
    vq_f16_kernel<<<mg, 256, SMEM_GEMM>>>();

    dim3 gg(B_ / 8, G_);
    rescore_gather_kernel<<<gg, 256>>>(feats, cb, out_q, out_idx);

    finalize_kernel<<<1, 256>>>(out_loss);
}

// round 10
// speedup vs baseline: 3.8982x; 1.0588x over previous
#include <cuda_runtime.h>
#include <cuda_fp16.h>
#include <cstdint>

#define G_ 10
#define B_ 32768
#define K_ 1024
#define D_ 256

// ==================== static device scratch ====================
__device__ float    g_rownorm[G_ * B_];
__device__ float    g_cbnorm [G_ * K_];
__device__ double   g_part   [G_ * (B_ / 8)];
__device__ uint32_t g_cand   [(size_t)G_ * B_ * 32];               // packed keys
// FP16 fragment-image copies: 4096 halves per (tile, 32d-chunk) block
__device__ __half   g_featsH[(size_t)G_ * (B_ / 128) * 8 * 4096];   // 168 MB
__device__ __half   g_cbH   [(size_t)G_ * 8 * 8 * 4096];            // 5.25 MB

// ==================== helpers ====================
__device__ __forceinline__ void mma_f16(float* c, const uint32_t* a, const uint32_t* b) {
    asm volatile(
        "mma.sync.aligned.m16n8k16.row.col.f32.f16.f16.f32 "
        "{%0,%1,%2,%3}, {%4,%5,%6,%7}, {%8,%9}, {%0,%1,%2,%3};"
        : "+f"(c[0]), "+f"(c[1]), "+f"(c[2]), "+f"(c[3])
        : "r"(a[0]), "r"(a[1]), "r"(a[2]), "r"(a[3]), "r"(b[0]), "r"(b[1]));
}
__device__ __forceinline__ uint32_t smem_u32(const void* p) {
    uint32_t a;
    asm("{ .reg .u64 t; cvta.to.shared.u64 t, %1; cvt.u32.u64 %0, t; }" : "=r"(a) : "l"(p));
    return a;
}
__device__ __forceinline__ void cp16(uint32_t dst, const void* src) {
    asm volatile("cp.async.cg.shared.global [%0], [%1], 16;" :: "r"(dst), "l"(src));
}
#define CP_COMMIT() asm volatile("cp.async.commit_group;" ::: "memory")
#define CP_WAIT2()  asm volatile("cp.async.wait_group 2;" ::: "memory")

// order-preserving float->uint key with 10-bit index in low bits
__device__ __forceinline__ uint32_t fkey(float v, int idx) {
    uint32_t b = __float_as_uint(v);
    uint32_t u = (b & 0x80000000u) ? ~b : (b | 0x80000000u);
    return (u & 0xFFFFFC00u) | (uint32_t)idx;
}
__device__ __forceinline__ float unkey(uint32_t key) {
    uint32_t u = key & 0xFFFFFC00u;
    uint32_t b = (u & 0x80000000u) ? (u ^ 0x80000000u) : ~u;
    return __uint_as_float(b);
}

// ==================== cbnorm (proven, bit-identical cn) ====================
__global__ void cbnorm_kernel(const float* __restrict__ cb) {
    int w = (blockIdx.x * 256 + threadIdx.x) >> 5;
    int lane = threadIdx.x & 31;
    const float4* r = (const float4*)(cb + (size_t)w * D_);
    float4 a = r[lane], b = r[lane + 32];
    float s = a.x*a.x + a.y*a.y + a.z*a.z + a.w*a.w
            + b.x*b.x + b.y*b.y + b.z*b.z + b.w*b.w;
#pragma unroll
    for (int off = 16; off; off >>= 1) s += __shfl_down_sync(0xffffffffu, s, off);
    if (!lane) g_cbnorm[w] = s;
}

// ==================== pre-format kernels (fp16 fragment images) ====================
// m16n8k16 fragment layouts (R9-validated):
//  A block: off = ks*2048 + (m>>4)*256 + lane*8 + reg*2 + half
//  B block: off = ks*2048 + (n>>3)*128 + lane*4 + reg*2 + half
// prep_feats ALSO computes rownorm with arithmetic bit-identical to the
// proven standalone rownorm_kernel (same expression, same shfl sequence).
__global__ void prep_feats_kernel(const float* __restrict__ feats) {
    __shared__ __align__(16) __half img[4096];
    const int tid = threadIdx.x;
    const int g = blockIdx.y, mt0 = blockIdx.x;
    const int srow = tid >> 1, ks = tid & 1;
    const int r = srow & 15, mt = srow >> 4;
    const float* Fb = feats + ((size_t)g * B_ + (mt0 << 7)) * D_;
    const float* F = Fb + (size_t)srow * D_;
    __half* dst = g_featsH + (size_t)(g * (B_ / 128) + mt0) * 8 * 4096;
    for (int c = 0; c < 8; ++c) {
        const float4* p = (const float4*)(F + (c << 5) + (ks << 4));
        float4 t0 = p[0], t1 = p[1], t2 = p[2], t3 = p[3];
        float v[16] = {t0.x,t0.y,t0.z,t0.w, t1.x,t1.y,t1.z,t1.w,
                       t2.x,t2.y,t2.z,t2.w, t3.x,t3.y,t3.z,t3.w};
#pragma unroll
        for (int jj = 0; jj < 16; jj += 2) {
            int lane = ((r & 7) << 2) | ((jj & 7) >> 1);
            int reg  = ((jj >> 3) << 1) | (r >> 3);
            int off  = ks * 2048 + mt * 256 + lane * 8 + reg * 2;
            *(__half2*)(img + off) = __floats2half2_rn(v[jj], v[jj + 1]);
        }
        __syncthreads();
        float4* o = (float4*)(dst + (size_t)c * 4096 + tid * 16);
        const float4* s = (const float4*)(img + tid * 16);
        o[0] = s[0]; o[1] = s[1];
        __syncthreads();
    }
    // ---- fused rownorm (identical arithmetic to proven rownorm_kernel) ----
    const int wid = tid >> 5, lane = tid & 31;
    for (int rr = 0; rr < 16; ++rr) {
        int row = (wid << 4) + rr;
        const float4* rp = (const float4*)(Fb + (size_t)row * D_);
        float4 a = rp[lane], b = rp[lane + 32];
        float s = a.x*a.x + a.y*a.y + a.z*a.z + a.w*a.w
                + b.x*b.x + b.y*b.y + b.z*b.z + b.w*b.w;
#pragma unroll
        for (int off = 16; off; off >>= 1) s += __shfl_down_sync(0xffffffffu, s, off);
        if (!lane) g_rownorm[(size_t)g * B_ + (mt0 << 7) + row] = s;
    }
}
__global__ void prep_cb_kernel(const float* __restrict__ cb) {
    __shared__ __align__(16) __half img[4096];
    const int tid = threadIdx.x;
    const int g = blockIdx.y, nt0 = blockIdx.x;
    const int n = tid >> 1, ks = tid & 1;
    const float* C = cb + (((size_t)g * K_ + (nt0 << 7)) + n) * D_;
    __half* dst = g_cbH + (size_t)(g * 8 + nt0) * 8 * 4096;
    for (int c = 0; c < 8; ++c) {
        const float4* p = (const float4*)(C + (c << 5) + (ks << 4));
        float4 t0 = p[0], t1 = p[1], t2 = p[2], t3 = p[3];
        float v[16] = {t0.x,t0.y,t0.z,t0.w, t1.x,t1.y,t1.z,t1.w,
                       t2.x,t2.y,t2.z,t2.w, t3.x,t3.y,t3.z,t3.w};
#pragma unroll
        for (int jj = 0; jj < 16; jj += 2) {
            int lane = ((n & 7) << 2) | ((jj & 7) >> 1);
            int reg  = jj >> 3;
            int off  = ks * 2048 + (n >> 3) * 128 + lane * 4 + reg * 2;
            *(__half2*)(img + off) = __floats2half2_rn(v[jj], v[jj + 1]);
        }
        __syncthreads();
        float4* o = (float4*)(dst + (size_t)c * 4096 + tid * 16);
        const float4* s = (const float4*)(img + tid * 16);
        o[0] = s[0]; o[1] = s[1];
        __syncthreads();
    }
}

// ==================== phase 1: fp16 GEMM, resident A + B ring ====================
// smem: A resident [8 chunks x 4096 halves = 64 KB] @0,
//       B ring     [4 stages x 4096 halves = 32 KB] @32768 halves.
// 64 chunks (8 ntiles x 8); B prefetch distance 3 (wait_group 2).
#define SMEM_GEMM (96 * 1024)

__global__ void __launch_bounds__(256, 2)
vq_f16_kernel() {
    extern __shared__ __half smh[];
    const uint32_t sb = smem_u32(smh);
    const int tid  = threadIdx.x;
    const int wid  = tid >> 5;
    const int lane = tid & 31;
    const int g    = blockIdx.y;
    const int mt0  = blockIdx.x;
    const int mw   = wid >> 1;
    const int nw   = wid & 1;

    const __half* srcA0 = g_featsH + (size_t)(g * (B_ / 128) + mt0) * 8 * 4096;
    const __half* srcB0 = g_cbH + (size_t)g * 8 * 8 * 4096;

    uint32_t L[4][4];
#pragma unroll
    for (int l = 0; l < 4; ++l)
#pragma unroll
        for (int s = 0; s < 4; ++s) L[l][s] = 0xFFFFFFFFu;

    float acc[2][8][4];
#pragma unroll
    for (int i = 0; i < 2; ++i)
#pragma unroll
        for (int j = 0; j < 8; ++j)
#pragma unroll
            for (int k = 0; k < 4; ++k) acc[i][j][k] = 0.0f;

    // prologue: A resident (one group), then B chunks 0..2 (one group each)
#pragma unroll
    for (int c = 0; c < 8; ++c) {
        uint32_t d = sb + c * 8192 + tid * 32;
        const __half* sa = srcA0 + (size_t)c * 4096 + tid * 16;
        cp16(d, sa); cp16(d + 16, sa + 8);
    }
    CP_COMMIT();
#pragma unroll
    for (int c = 0; c < 3; ++c) {
        uint32_t d = sb + 65536 + c * 8192 + tid * 32;
        const __half* sbp = srcB0 + (size_t)c * 4096 + tid * 16;
        cp16(d, sbp); cp16(d + 16, sbp + 8);
        CP_COMMIT();
    }

    for (int cc = 0; cc < 64; ++cc) {
        CP_WAIT2();
        __syncthreads();
        const __half* bufA = smh + (cc & 7) * 4096;
        const __half* bufB = smh + 32768 + (cc & 3) * 4096;

        // ---- MMA on chunk cc (R9-validated fragment reads) ----
#pragma unroll
        for (int ks = 0; ks < 2; ++ks) {
            uint32_t aF[2][4];
#pragma unroll
            for (int mti = 0; mti < 2; ++mti) {
                uint4 t = *(const uint4*)(bufA + ks * 2048 + ((mw << 1) + mti) * 256 + lane * 8);
                aF[mti][0] = t.x; aF[mti][1] = t.y; aF[mti][2] = t.z; aF[mti][3] = t.w;
            }
#pragma unroll
            for (int nt = 0; nt < 8; ++nt) {
                uint2 bt = *(const uint2*)(bufB + ks * 2048 + ((nw << 3) + nt) * 128 + lane * 4);
                uint32_t bF[2] = {bt.x, bt.y};
                mma_f16(acc[0][nt], aF[0], bF);
                mma_f16(acc[1][nt], aF[1], bF);
            }
        }

        // ---- refill B stage cc+3 (chunk index is linear in g_cbH) ----
        if (cc + 3 < 64) {
            const int nc = cc + 3;
            uint32_t d = sb + 65536 + (nc & 3) * 8192 + tid * 32;
            const __half* sbp = srcB0 + (size_t)nc * 4096 + tid * 16;
            cp16(d, sbp); cp16(d + 16, sbp + 8);
        }
        CP_COMMIT();

        // ---- epilogue at end of each ntile (every 8 chunks) ----
        if ((cc & 7) == 7) {
            const int ntile = cc >> 3;
            const float* cnb = g_cbnorm + (size_t)g * K_ + (ntile << 7);
#pragma unroll
            for (int nt = 0; nt < 8; ++nt) {
                int cl = (nw << 6) + (nt << 3) + ((lane & 3) << 1);
                float cn0 = __ldg(cnb + cl), cn1 = __ldg(cnb + cl + 1);
                int gi = (ntile << 7) + cl;
#pragma unroll
                for (int l = 0; l < 4; ++l) {
                    const int mti = l >> 1, hf = l & 1;
                    float v0 = cn0 - 2.0f * acc[mti][nt][(hf << 1)];
                    float v1 = cn1 - 2.0f * acc[mti][nt][(hf << 1) + 1];
                    uint32_t k0 = fkey(v0, gi), k1 = fkey(v1, gi + 1);
#pragma unroll
                    for (int pick = 0; pick < 2; ++pick) {
                        uint32_t k = pick ? k1 : k0;
                        if (k < L[l][3]) {
                            if (k < L[l][2]) {
                                L[l][3] = L[l][2];
                                if (k < L[l][1]) {
                                    L[l][2] = L[l][1];
                                    if (k < L[l][0]) { L[l][1] = L[l][0]; L[l][0] = k; }
                                    else             { L[l][1] = k; }
                                } else { L[l][2] = k; }
                            } else { L[l][3] = k; }
                        }
                    }
                }
            }
#pragma unroll
            for (int i = 0; i < 2; ++i)
#pragma unroll
                for (int j = 0; j < 8; ++j)
#pragma unroll
                    for (int k = 0; k < 4; ++k) acc[i][j][k] = 0.0f;
        }
    }

    // ---- dump 32 keys per row ----
#pragma unroll
    for (int l = 0; l < 4; ++l) {
        const int mti = l >> 1, hf = l & 1;
        int rloc = (mw << 5) + (mti << 4) + (hf << 3) + (lane >> 2);
        size_t r = (size_t)g * B_ + (mt0 << 7) + rloc;
        int s8 = (nw << 2) | (lane & 3);
#pragma unroll
        for (int s = 0; s < 4; ++s)
            g_cand[r * 32 + s8 * 4 + s] = L[l][s];
    }
}

// ==================== phase 2: exact fp32 rescore + gather + loss ====================
#define EPS_RESCORE 0.03f

__global__ void rescore_gather_kernel(const float* __restrict__ feats,
                                      const float* __restrict__ cb,
                                      float* __restrict__ out_q,
                                      float* __restrict__ out_idx_f) {
    __shared__ double bs[8];
    const int g = blockIdx.y, w = threadIdx.x >> 5, lane = threadIdx.x & 31;
    const size_t row = (size_t)g * B_ + ((size_t)blockIdx.x << 3) + w;

    uint32_t key = g_cand[row * 32 + lane];
    int   ci = (int)(key & 1023u);
    float cv = unkey(key);

    uint32_t kmin = key;
#pragma unroll
    for (int off = 16; off; off >>= 1)
        kmin = min(kmin, __shfl_xor_sync(0xffffffffu, kmin, off));
    float vminf = unkey(kmin);
    unsigned mask = __ballot_sync(0xffffffffu, cv <= vminf + EPS_RESCORE);

    const float4* f4 = (const float4*)(feats + row * D_);
    int bestI;
    if (__popc(mask) == 1) {
        // single candidate within EPS of the approx min: it IS the winner
        // (same pruning assumption as the proven multi-candidate path).
        bestI = (int)(kmin & 1023u);
    } else {
        float4 fa = f4[lane * 2], fb = f4[lane * 2 + 1];
        const float rn = g_rownorm[row];
        float bestV = 3.4e38f;
        bestI = 0x7fffffff;
        unsigned m = mask;
        while (m) {
            int j = __ffs(m) - 1;
            m &= m - 1;
            int idx = __shfl_sync(0xffffffffu, ci, j);
            const float4* c4 = (const float4*)(cb + ((size_t)g * K_ + idx) * D_);
            float4 ca = c4[lane * 2], cbv = c4[lane * 2 + 1];
            float p = fa.x*ca.x + fa.y*ca.y + fa.z*ca.z + fa.w*ca.w
                    + fb.x*cbv.x + fb.y*cbv.y + fb.z*cbv.z + fb.w*cbv.w;
#pragma unroll
            for (int off = 16; off; off >>= 1) p += __shfl_xor_sync(0xffffffffu, p, off);
            float cn = g_cbnorm[(size_t)g * K_ + idx];
            float d2 = (rn + cn) - 2.0f * p;       // reference rounding structure
            if (d2 < bestV || (d2 == bestV && idx < bestI)) { bestV = d2; bestI = idx; }
        }
    }

    const float4* q4 = (const float4*)(cb + ((size_t)g * K_ + bestI) * D_);
    float4* o4 = (float4*)(out_q + row * D_);
    float sl = 0.0f;
#pragma unroll
    for (int it = 0; it < 2; ++it) {
        int p = lane + (it << 5);
        float4 f = f4[p], q = q4[p], o;
        float t;
        t = q.x - f.x; o.x = f.x + t; sl += t * t;
        t = q.y - f.y; o.y = f.y + t; sl += t * t;
        t = q.z - f.z; o.z = f.z + t; sl += t * t;
        t = q.w - f.w; o.w = f.w + t; sl += t * t;
        o4[p] = o;
    }
    double s = (double)sl;
#pragma unroll
    for (int off = 16; off; off >>= 1) s += __shfl_down_sync(0xffffffffu, s, off);
    if (!lane) {
        bs[w] = s;
        out_idx_f[row] = (float)bestI;
    }
    __syncthreads();
    if (!threadIdx.x) {
        double tot = 0.0;
#pragma unroll
        for (int i = 0; i < 8; i++) tot += bs[i];
        g_part[(size_t)g * (B_ / 8) + blockIdx.x] = tot;
    }
}

// ==================== deterministic loss finalize (proven) ====================
__global__ void finalize_kernel(float* __restrict__ out_loss) {
    __shared__ double sh[256];
    __shared__ float gm[G_];
    int tid = threadIdx.x;
    for (int g = 0; g < G_; ++g) {
        double s = 0.0;
        for (int i = tid; i < B_ / 8; i += 256) s += g_part[(size_t)g * (B_ / 8) + i];
        sh[tid] = s;
        __syncthreads();
        for (int st = 128; st; st >>= 1) {
            if (tid < st) sh[tid] += sh[tid + st];
            __syncthreads();
        }
        if (!tid) gm[g] = (float)(sh[0] / (double)((size_t)B_ * D_));
        __syncthreads();
    }
    if (!tid) {
        const float commit[G_] = {0.5f, 0.5f, 0.4f, 0.4f, 0.4f,
                                  0.4f, 0.8f, 0.8f, 0.8f, 0.8f};
        float total = 0.0f;
        for (int g = 0; g < G_; ++g) {
            float e = gm[g];
            total += e + commit[g] * e;
        }
        *out_loss = total;
    }
}

// ==================== launch ====================
extern "C" void kernel_launch(void* const* d_in, const int* in_sizes, int n_in,
                              void* d_out, int out_size) {
    (void)in_sizes; (void)n_in; (void)out_size;
    const float* feats = (const float*)d_in[0];
    const float* cb    = (const float*)d_in[1];
    float* out      = (float*)d_out;
    float* out_q    = out;
    float* out_loss = out + (size_t)G_ * B_ * D_;
    float* out_idx  = out_loss + 1;

    cudaFuncSetAttribute(vq_f16_kernel, cudaFuncAttributeMaxDynamicSharedMemorySize,
                         SMEM_GEMM);

    cbnorm_kernel<<<G_ * K_ / 8, 256>>>(cb);

    dim3 pf(B_ / 128, G_);
    prep_feats_kernel<<<pf, 256>>>(feats);   // also writes g_rownorm
    dim3 pc(8, G_);
    prep_cb_kernel<<<pc, 256>>>(cb);

    dim3 mg(B_ / 128, G_);
    vq_f16_kernel<<<mg, 256, SMEM_GEMM>>>();

    dim3 gg(B_ / 8, G_);
    rescore_gather_kernel<<<gg, 256>>>(feats, cb, out_q, out_idx);

    finalize_kernel<<<1, 256>>>(out_loss);
}

// round 12
// speedup vs baseline: 3.9471x; 1.0126x over previous
#include <cuda_runtime.h>
#include <cuda_fp16.h>
#include <cstdint>

#define G_ 10
#define B_ 32768
#define K_ 1024
#define D_ 256

// ==================== static device scratch ====================
__device__ float    g_rownorm[G_ * B_];
__device__ float    g_cbnorm [G_ * K_];
__device__ double   g_part   [G_ * (B_ / 8)];
__device__ uint32_t g_cand   [(size_t)G_ * B_ * 32];               // packed keys
// FP16 fragment-image copies: 4096 halves per (tile, 32d-chunk) block
__device__ __half   g_featsH[(size_t)G_ * (B_ / 128) * 8 * 4096];   // 168 MB
__device__ __half   g_cbH   [(size_t)G_ * 8 * 8 * 4096];            // 5.25 MB

// ==================== helpers ====================
__device__ __forceinline__ void mma_f16(float* c, const uint32_t* a, const uint32_t* b) {
    asm volatile(
        "mma.sync.aligned.m16n8k16.row.col.f32.f16.f16.f32 "
        "{%0,%1,%2,%3}, {%4,%5,%6,%7}, {%8,%9}, {%0,%1,%2,%3};"
        : "+f"(c[0]), "+f"(c[1]), "+f"(c[2]), "+f"(c[3])
        : "r"(a[0]), "r"(a[1]), "r"(a[2]), "r"(a[3]), "r"(b[0]), "r"(b[1]));
}
__device__ __forceinline__ uint32_t smem_u32(const void* p) {
    uint32_t a;
    asm("{ .reg .u64 t; cvta.to.shared.u64 t, %1; cvt.u32.u64 %0, t; }" : "=r"(a) : "l"(p));
    return a;
}
__device__ __forceinline__ void cp16(uint32_t dst, const void* src) {
    asm volatile("cp.async.cg.shared.global [%0], [%1], 16;" :: "r"(dst), "l"(src));
}
#define CP_COMMIT() asm volatile("cp.async.commit_group;" ::: "memory")
#define CP_WAIT1()  asm volatile("cp.async.wait_group 1;" ::: "memory")

// order-preserving float->uint key with 10-bit index in low bits (R9/R10-proven)
__device__ __forceinline__ uint32_t fkey(float v, int idx) {
    uint32_t b = __float_as_uint(v);
    uint32_t u = (b & 0x80000000u) ? ~b : (b | 0x80000000u);
    return (u & 0xFFFFFC00u) | (uint32_t)idx;
}
__device__ __forceinline__ float unkey(uint32_t key) {
    uint32_t u = key & 0xFFFFFC00u;
    uint32_t b = (u & 0x80000000u) ? (u ^ 0x80000000u) : ~u;
    return __uint_as_float(b);
}

// ==================== cbnorm (proven, bit-identical cn) ====================
__global__ void cbnorm_kernel(const float* __restrict__ cb) {
    int w = (blockIdx.x * 256 + threadIdx.x) >> 5;
    int lane = threadIdx.x & 31;
    const float4* r = (const float4*)(cb + (size_t)w * D_);
    float4 a = r[lane], b = r[lane + 32];
    float s = a.x*a.x + a.y*a.y + a.z*a.z + a.w*a.w
            + b.x*b.x + b.y*b.y + b.z*b.z + b.w*b.w;
#pragma unroll
    for (int off = 16; off; off >>= 1) s += __shfl_down_sync(0xffffffffu, s, off);
    if (!lane) g_cbnorm[w] = s;
}

// ==================== pre-format kernels (fp16 fragment images) ====================
// A block (R9/R10-validated): off = ks*2048 + (m>>4)*256 + lane*8 + reg*2 + half
// B block (R11-validated pairing, for LDS.128 of two adjacent 8-col groups):
//   p=n>>4, q=(n>>3)&1: off = ks*2048 + p*256 + lane*8 + q*4 + reg*2 + half
// prep_feats ALSO computes rownorm bit-identical to the proven rownorm_kernel.
__global__ void prep_feats_kernel(const float* __restrict__ feats) {
    __shared__ __align__(16) __half img[4096];
    const int tid = threadIdx.x;
    const int g = blockIdx.y, mt0 = blockIdx.x;
    const int srow = tid >> 1, ks = tid & 1;
    const int r = srow & 15, mt = srow >> 4;
    const float* Fb = feats + ((size_t)g * B_ + (mt0 << 7)) * D_;
    const float* F = Fb + (size_t)srow * D_;
    __half* dst = g_featsH + (size_t)(g * (B_ / 128) + mt0) * 8 * 4096;
    for (int c = 0; c < 8; ++c) {
        const float4* p = (const float4*)(F + (c << 5) + (ks << 4));
        float4 t0 = p[0], t1 = p[1], t2 = p[2], t3 = p[3];
        float v[16] = {t0.x,t0.y,t0.z,t0.w, t1.x,t1.y,t1.z,t1.w,
                       t2.x,t2.y,t2.z,t2.w, t3.x,t3.y,t3.z,t3.w};
#pragma unroll
        for (int jj = 0; jj < 16; jj += 2) {
            int lane = ((r & 7) << 2) | ((jj & 7) >> 1);
            int reg  = ((jj >> 3) << 1) | (r >> 3);
            int off  = ks * 2048 + mt * 256 + lane * 8 + reg * 2;
            *(__half2*)(img + off) = __floats2half2_rn(v[jj], v[jj + 1]);
        }
        __syncthreads();
        float4* o = (float4*)(dst + (size_t)c * 4096 + tid * 16);
        const float4* s = (const float4*)(img + tid * 16);
        o[0] = s[0]; o[1] = s[1];
        __syncthreads();
    }
    // ---- fused rownorm (identical arithmetic to proven rownorm_kernel) ----
    const int wid = tid >> 5, lane = tid & 31;
    for (int rr = 0; rr < 16; ++rr) {
        int row = (wid << 4) + rr;
        const float4* rp = (const float4*)(Fb + (size_t)row * D_);
        float4 a = rp[lane], b = rp[lane + 32];
        float s = a.x*a.x + a.y*a.y + a.z*a.z + a.w*a.w
                + b.x*b.x + b.y*b.y + b.z*b.z + b.w*b.w;
#pragma unroll
        for (int off = 16; off; off >>= 1) s += __shfl_down_sync(0xffffffffu, s, off);
        if (!lane) g_rownorm[(size_t)g * B_ + (mt0 << 7) + row] = s;
    }
}
__global__ void prep_cb_kernel(const float* __restrict__ cb) {
    __shared__ __align__(16) __half img[4096];
    const int tid = threadIdx.x;
    const int g = blockIdx.y, nt0 = blockIdx.x;
    const int n = tid >> 1, ks = tid & 1;
    const int pP = n >> 4, qQ = (n >> 3) & 1;
    const float* C = cb + (((size_t)g * K_ + (nt0 << 7)) + n) * D_;
    __half* dst = g_cbH + (size_t)(g * 8 + nt0) * 8 * 4096;
    for (int c = 0; c < 8; ++c) {
        const float4* p = (const float4*)(C + (c << 5) + (ks << 4));
        float4 t0 = p[0], t1 = p[1], t2 = p[2], t3 = p[3];
        float v[16] = {t0.x,t0.y,t0.z,t0.w, t1.x,t1.y,t1.z,t1.w,
                       t2.x,t2.y,t2.z,t2.w, t3.x,t3.y,t3.z,t3.w};
#pragma unroll
        for (int jj = 0; jj < 16; jj += 2) {
            int lane = ((n & 7) << 2) | ((jj & 7) >> 1);
            int reg  = jj >> 3;
            int off  = ks * 2048 + pP * 256 + lane * 8 + qQ * 4 + reg * 2;
            *(__half2*)(img + off) = __floats2half2_rn(v[jj], v[jj + 1]);
        }
        __syncthreads();
        float4* o = (float4*)(dst + (size_t)c * 4096 + tid * 16);
        const float4* s = (const float4*)(img + tid * 16);
        o[0] = s[0]; o[1] = s[1];
        __syncthreads();
    }
}

// ==================== phase 1: fp16 GEMM, resident A + 3-stage B ring ====================
// smem: A resident [8 x 4096 halves = 64 KB] @0,
//       B ring     [3 stages x 8192 halves (= 2 chunks) = 48 KB] @32768 halves.
// 32 iterations of 64 d; per-score top-4 epilogue (R10-proven) every 4 iters.
#define SMEM_GEMM (112 * 1024)

__global__ void __launch_bounds__(256, 2)
vq_f16_kernel() {
    extern __shared__ __half smh[];
    const uint32_t sb = smem_u32(smh);
    const int tid  = threadIdx.x;
    const int wid  = tid >> 5;
    const int lane = tid & 31;
    const int g    = blockIdx.y;
    const int mt0  = blockIdx.x;
    const int mw   = wid >> 1;
    const int nw   = wid & 1;

    const __half* srcA0 = g_featsH + (size_t)(g * (B_ / 128) + mt0) * 8 * 4096;
    const __half* srcB0 = g_cbH + (size_t)g * 8 * 8 * 4096;

    uint32_t L[4][4];
#pragma unroll
    for (int l = 0; l < 4; ++l)
#pragma unroll
        for (int s = 0; s < 4; ++s) L[l][s] = 0xFFFFFFFFu;

    float acc[2][8][4];
#pragma unroll
    for (int i = 0; i < 2; ++i)
#pragma unroll
        for (int j = 0; j < 8; ++j)
#pragma unroll
            for (int k = 0; k < 4; ++k) acc[i][j][k] = 0.0f;

    // prologue: resident A (1 group), then B stages 0,1 (1 group each)
#pragma unroll
    for (int c = 0; c < 8; ++c) {
        uint32_t d = sb + c * 8192 + tid * 32;
        const __half* sa = srcA0 + (size_t)c * 4096 + tid * 16;
        cp16(d, sa); cp16(d + 16, sa + 8);
    }
    CP_COMMIT();
#pragma unroll
    for (int s = 0; s < 2; ++s) {
        uint32_t d = sb + 65536 + s * 16384 + tid * 64;
        const __half* sbp = srcB0 + (size_t)s * 8192 + tid * 32;
        cp16(d, sbp); cp16(d + 16, sbp + 8);
        cp16(d + 32, sbp + 16); cp16(d + 48, sbp + 24);
        CP_COMMIT();
    }

    for (int i = 0; i < 32; ++i) {
        CP_WAIT1();
        __syncthreads();
        const __half* bufBs = smh + 32768 + (i % 3) * 8192;

        // ---- MMA on two 32-d sub-chunks (R11-validated reads) ----
#pragma unroll
        for (int u = 0; u < 2; ++u) {
            const __half* bufA = smh + (((i << 1) + u) & 7) * 4096;
            const __half* bufB = bufBs + (u << 12);
#pragma unroll
            for (int ks = 0; ks < 2; ++ks) {
                uint32_t aF[2][4];
#pragma unroll
                for (int mti = 0; mti < 2; ++mti) {
                    uint4 t = *(const uint4*)(bufA + ks * 2048 + ((mw << 1) + mti) * 256 + lane * 8);
                    aF[mti][0] = t.x; aF[mti][1] = t.y; aF[mti][2] = t.z; aF[mti][3] = t.w;
                }
#pragma unroll
                for (int pp = 0; pp < 4; ++pp) {
                    uint4 bt = *(const uint4*)(bufB + ks * 2048 + ((nw << 2) + pp) * 256 + lane * 8);
                    uint32_t b0[2] = {bt.x, bt.y};
                    uint32_t b1[2] = {bt.z, bt.w};
                    mma_f16(acc[0][(pp << 1)],     aF[0], b0);
                    mma_f16(acc[1][(pp << 1)],     aF[1], b0);
                    mma_f16(acc[0][(pp << 1) + 1], aF[0], b1);
                    mma_f16(acc[1][(pp << 1) + 1], aF[1], b1);
                }
            }
        }

        // ---- refill B stage i+2 ----
        if (i + 2 < 32) {
            const int s = (i + 2) % 3;
            uint32_t d = sb + 65536 + s * 16384 + tid * 64;
            const __half* sbp = srcB0 + (size_t)(i + 2) * 8192 + tid * 32;
            cp16(d, sbp); cp16(d + 16, sbp + 8);
            cp16(d + 32, sbp + 16); cp16(d + 48, sbp + 24);
        }
        CP_COMMIT();

        // ---- epilogue every 4 iters: per-score top-4 insertion (R10 logic,
        //      R11-validated paired column mapping) ----
        if ((i & 3) == 3) {
            const int ntile = i >> 2;
            const float* cnb = g_cbnorm + (size_t)g * K_ + (ntile << 7);
#pragma unroll
            for (int p = 0; p < 4; ++p) {
                int cl0 = (nw << 6) + (p << 4) + ((lane & 3) << 1);
                float2 cnA = __ldg((const float2*)(cnb + cl0));
                float2 cnB = __ldg((const float2*)(cnb + cl0 + 8));
                int gi0 = (ntile << 7) + cl0;
                int gi1 = gi0 + 8;
#pragma unroll
                for (int l = 0; l < 4; ++l) {
                    const int mti = l >> 1, hf = l & 1;
                    float sc[4];
                    int   gi[4];
                    sc[0] = cnA.x - 2.0f * acc[mti][(p << 1)][(hf << 1)];     gi[0] = gi0;
                    sc[1] = cnA.y - 2.0f * acc[mti][(p << 1)][(hf << 1) + 1]; gi[1] = gi0 + 1;
                    sc[2] = cnB.x - 2.0f * acc[mti][(p << 1) + 1][(hf << 1)];     gi[2] = gi1;
                    sc[3] = cnB.y - 2.0f * acc[mti][(p << 1) + 1][(hf << 1) + 1]; gi[3] = gi1 + 1;
#pragma unroll
                    for (int q = 0; q < 4; ++q) {
                        uint32_t k = fkey(sc[q], gi[q]);
                        if (k < L[l][3]) {
                            if (k < L[l][2]) {
                                L[l][3] = L[l][2];
                                if (k < L[l][1]) {
                                    L[l][2] = L[l][1];
                                    if (k < L[l][0]) { L[l][1] = L[l][0]; L[l][0] = k; }
                                    else             { L[l][1] = k; }
                                } else { L[l][2] = k; }
                            } else { L[l][3] = k; }
                        }
                    }
                }
            }
#pragma unroll
            for (int a = 0; a < 2; ++a)
#pragma unroll
                for (int j = 0; j < 8; ++j)
#pragma unroll
                    for (int k = 0; k < 4; ++k) acc[a][j][k] = 0.0f;
        }
    }

    // ---- dump 32 keys per row ----
#pragma unroll
    for (int l = 0; l < 4; ++l) {
        const int mti = l >> 1, hf = l & 1;
        int rloc = (mw << 5) + (mti << 4) + (hf << 3) + (lane >> 2);
        size_t r = (size_t)g * B_ + (mt0 << 7) + rloc;
        int s8 = (nw << 2) | (lane & 3);
#pragma unroll
        for (int s = 0; s < 4; ++s)
            g_cand[r * 32 + s8 * 4 + s] = L[l][s];
    }
}

// ==================== phase 2: exact fp32 rescore + gather + loss (proven) ====================
#define EPS_RESCORE 0.03f

__global__ void rescore_gather_kernel(const float* __restrict__ feats,
                                      const float* __restrict__ cb,
                                      float* __restrict__ out_q,
                                      float* __restrict__ out_idx_f) {
    __shared__ double bs[8];
    const int g = blockIdx.y, w = threadIdx.x >> 5, lane = threadIdx.x & 31;
    const size_t row = (size_t)g * B_ + ((size_t)blockIdx.x << 3) + w;

    uint32_t key = g_cand[row * 32 + lane];
    int   ci = (int)(key & 1023u);
    float cv = unkey(key);

    uint32_t kmin = key;
#pragma unroll
    for (int off = 16; off; off >>= 1)
        kmin = min(kmin, __shfl_xor_sync(0xffffffffu, kmin, off));
    float vminf = unkey(kmin);
    unsigned mask = __ballot_sync(0xffffffffu, cv <= vminf + EPS_RESCORE);

    const float4* f4 = (const float4*)(feats + row * D_);
    int bestI;
    if (__popc(mask) == 1) {
        bestI = (int)(kmin & 1023u);
    } else {
        float4 fa = f4[lane * 2], fb = f4[lane * 2 + 1];
        const float rn = g_rownorm[row];
        float bestV = 3.4e38f;
        bestI = 0x7fffffff;
        unsigned m = mask;
        while (m) {
            int j = __ffs(m) - 1;
            m &= m - 1;
            int idx = __shfl_sync(0xffffffffu, ci, j);
            const float4* c4 = (const float4*)(cb + ((size_t)g * K_ + idx) * D_);
            float4 ca = c4[lane * 2], cbv = c4[lane * 2 + 1];
            float p = fa.x*ca.x + fa.y*ca.y + fa.z*ca.z + fa.w*ca.w
                    + fb.x*cbv.x + fb.y*cbv.y + fb.z*cbv.z + fb.w*cbv.w;
#pragma unroll
            for (int off = 16; off; off >>= 1) p += __shfl_xor_sync(0xffffffffu, p, off);
            float cn = g_cbnorm[(size_t)g * K_ + idx];
            float d2 = (rn + cn) - 2.0f * p;       // reference rounding structure
            if (d2 < bestV || (d2 == bestV && idx < bestI)) { bestV = d2; bestI = idx; }
        }
    }

    const float4* q4 = (const float4*)(cb + ((size_t)g * K_ + bestI) * D_);
    float4* o4 = (float4*)(out_q + row * D_);
    float sl = 0.0f;
#pragma unroll
    for (int it = 0; it < 2; ++it) {
        int p = lane + (it << 5);
        float4 f = f4[p], q = q4[p], o;
        float t;
        t = q.x - f.x; o.x = f.x + t; sl += t * t;
        t = q.y - f.y; o.y = f.y + t; sl += t * t;
        t = q.z - f.z; o.z = f.z + t; sl += t * t;
        t = q.w - f.w; o.w = f.w + t; sl += t * t;
        o4[p] = o;
    }
    double s = (double)sl;
#pragma unroll
    for (int off = 16; off; off >>= 1) s += __shfl_down_sync(0xffffffffu, s, off);
    if (!lane) {
        bs[w] = s;
        out_idx_f[row] = (float)bestI;
    }
    __syncthreads();
    if (!threadIdx.x) {
        double tot = 0.0;
#pragma unroll
        for (int i = 0; i < 8; i++) tot += bs[i];
        g_part[(size_t)g * (B_ / 8) + blockIdx.x] = tot;
    }
}

// ==================== deterministic loss finalize (proven) ====================
__global__ void finalize_kernel(float* __restrict__ out_loss) {
    __shared__ double sh[256];
    __shared__ float gm[G_];
    int tid = threadIdx.x;
    for (int g = 0; g < G_; ++g) {
        double s = 0.0;
        for (int i = tid; i < B_ / 8; i += 256) s += g_part[(size_t)g * (B_ / 8) + i];
        sh[tid] = s;
        __syncthreads();
        for (int st = 128; st; st >>= 1) {
            if (tid < st) sh[tid] += sh[tid + st];
            __syncthreads();
        }
        if (!tid) gm[g] = (float)(sh[0] / (double)((size_t)B_ * D_));
        __syncthreads();
    }
    if (!tid) {
        const float commit[G_] = {0.5f, 0.5f, 0.4f, 0.4f, 0.4f,
                                  0.4f, 0.8f, 0.8f, 0.8f, 0.8f};
        float total = 0.0f;
        for (int g = 0; g < G_; ++g) {
            float e = gm[g];
            total += e + commit[g] * e;
        }
        *out_loss = total;
    }
}

// ==================== launch ====================
extern "C" void kernel_launch(void* const* d_in, const int* in_sizes, int n_in,
                              void* d_out, int out_size) {
    (void)in_sizes; (void)n_in; (void)out_size;
    const float* feats = (const float*)d_in[0];
    const float* cb    = (const float*)d_in[1];
    float* out      = (float*)d_out;
    float* out_q    = out;
    float* out_loss = out + (size_t)G_ * B_ * D_;
    float* out_idx  = out_loss + 1;

    cudaFuncSetAttribute(vq_f16_kernel, cudaFuncAttributeMaxDynamicSharedMemorySize,
                         SMEM_GEMM);

    cbnorm_kernel<<<G_ * K_ / 8, 256>>>(cb);

    dim3 pf(B_ / 128, G_);
    prep_feats_kernel<<<pf, 256>>>(feats);   // also writes g_rownorm
    dim3 pc(8, G_);
    prep_cb_kernel<<<pc, 256>>>(cb);

    dim3 mg(B_ / 128, G_);
    vq_f16_kernel<<<mg, 256, SMEM_GEMM>>>();

    dim3 gg(B_ / 8, G_);
    rescore_gather_kernel<<<gg, 256>>>(feats, cb, out_q, out_idx);

    finalize_kernel<<<1, 256>>>(out_loss);
}